// round 2
// baseline (speedup 1.0000x reference)
#include <cuda_runtime.h>
#include <math.h>

#define NN   50000
#define EE   400000
#define FINN 22
#define EDIM 22
#define HH   8
#define D1   256
#define D2   512
#define QPW  176    /* 8 heads * 22 attr dims */

#define W1COLS 1200    /* 4*256 + 176 */
#define W2COLS 2304    /* 4*512 + 176, padded to 18*128 */
#define W2VALID 2224

#define SCAP 256       /* smem alpha capacity per dst */

// ---------------- scratch (device globals; no allocations allowed) ----------
__device__ float g_q1[NN * D1];
__device__ float g_k1[NN * D1];
__device__ float g_v1[NN * D1];
__device__ float g_x1[NN * D1];
__device__ float g_qp1[NN * QPW];
__device__ float g_q2[NN * D2];
__device__ float g_k2[NN * D2];
__device__ float g_v2[NN * D2];
__device__ float g_x2[NN * D2];
__device__ float g_qp2[NN * QPW];
__device__ float g_alpha[EE * HH];
__device__ int   g_deg[NN];
__device__ int   g_cur[NN];
__device__ int   g_off[NN + 1];
__device__ int   g_csrc[EE];
__device__ int   g_ceid[EE];
__device__ float g_wcat1[FINN * W1COLS];
__device__ float g_bcat1[W1COLS];
__device__ float g_wcat2[D1 * W2COLS];
__device__ float g_bcat2[W2COLS];
__device__ int   g_is64;

// ---------------- edge_index dtype detection (int32 vs int64) ---------------
// If the buffer is int64 (values < 2^31, LE), every odd 32-bit word of the
// first 2048 words is a zero high-half. For int32 data those words are random
// node ids (~1/50000 chance each of being 0), so requiring ALL zero is safe.
__global__ void k_detect(const int* __restrict__ ei) {
    if (threadIdx.x == 0 && blockIdx.x == 0) {
        int all_zero = 1;
        for (int i = 0; i < 1024; i++) {
            if (ei[2 * i + 1] != 0) { all_zero = 0; break; }
        }
        g_is64 = all_zero;
    }
}

__device__ __forceinline__ int ld_src(const int* __restrict__ ei, int e) {
    return g_is64 ? ei[2 * e] : ei[e];
}
__device__ __forceinline__ int ld_dst(const int* __restrict__ ei, int e) {
    return g_is64 ? ei[2 * (EE + e)] : ei[EE + e];
}

// ---------------- CSR build ----------------
__global__ void k_zero_counters() {
    int i = blockIdx.x * blockDim.x + threadIdx.x;
    if (i < NN) { g_deg[i] = 0; g_cur[i] = 0; }
}

__global__ void k_hist(const int* __restrict__ ei) {
    int e = blockIdx.x * blockDim.x + threadIdx.x;
    if (e < EE) {
        int dst = ld_dst(ei, e);
        atomicAdd(&g_deg[dst], 1);
    }
}

__global__ void k_scan() {   // 1 block, 1024 threads
    __shared__ int sm[1024];
    __shared__ int running;
    if (threadIdx.x == 0) { running = 0; g_off[0] = 0; }
    __syncthreads();
    for (int base = 0; base < NN; base += 1024) {
        int i = base + threadIdx.x;
        int v = (i < NN) ? g_deg[i] : 0;
        sm[threadIdx.x] = v;
        __syncthreads();
        for (int off = 1; off < 1024; off <<= 1) {
            int t = 0;
            if (threadIdx.x >= off) t = sm[threadIdx.x - off];
            __syncthreads();
            if (threadIdx.x >= off) sm[threadIdx.x] += t;
            __syncthreads();
        }
        if (i < NN) g_off[i + 1] = running + sm[threadIdx.x];
        __syncthreads();
        if (threadIdx.x == 0) running += sm[1023];
        __syncthreads();
    }
}

__global__ void k_scatter(const int* __restrict__ ei) {
    int e = blockIdx.x * blockDim.x + threadIdx.x;
    if (e < EE) {
        int src = ld_src(ei, e);
        int dst = ld_dst(ei, e);
        int pos = g_off[dst] + atomicAdd(&g_cur[dst], 1);
        g_csrc[pos] = src;
        g_ceid[pos] = e;
    }
}

// ---------------- weight concat builders (fold qproj = (x@Wq+b)@We_h^T) ----
__global__ void k_wcat1(const float* __restrict__ wq, const float* __restrict__ bq,
                        const float* __restrict__ wk, const float* __restrict__ bk,
                        const float* __restrict__ wv, const float* __restrict__ bv,
                        const float* __restrict__ we,
                        const float* __restrict__ ws, const float* __restrict__ bs) {
    int idx = blockIdx.x * blockDim.x + threadIdx.x;
    int wn = FINN * W1COLS;
    if (idx < wn) {
        int f = idx / W1COLS, c = idx % W1COLS;
        float val;
        if (c < 256)       val = wq[f * 256 + c];
        else if (c < 512)  val = wk[f * 256 + (c - 256)];
        else if (c < 768)  val = wv[f * 256 + (c - 512)];
        else if (c < 1024) val = ws[f * 256 + (c - 768)];
        else {
            int t = c - 1024, h = t / 22, g = t % 22;
            float s = 0.f;
            for (int cc = 0; cc < 32; cc++)
                s += wq[f * 256 + h * 32 + cc] * we[g * 256 + h * 32 + cc];
            val = s;
        }
        g_wcat1[f * W1COLS + c] = val;
    } else if (idx < wn + W1COLS) {
        int c = idx - wn;
        float val;
        if (c < 256)       val = bq[c];
        else if (c < 512)  val = bk[c - 256];
        else if (c < 768)  val = bv[c - 512];
        else if (c < 1024) val = bs[c - 768];
        else {
            int t = c - 1024, h = t / 22, g = t % 22;
            float s = 0.f;
            for (int cc = 0; cc < 32; cc++)
                s += bq[h * 32 + cc] * we[g * 256 + h * 32 + cc];
            val = s;
        }
        g_bcat1[c] = val;
    }
}

__global__ void k_wcat2(const float* __restrict__ wq, const float* __restrict__ bq,
                        const float* __restrict__ wk, const float* __restrict__ bk,
                        const float* __restrict__ wv, const float* __restrict__ bv,
                        const float* __restrict__ we,
                        const float* __restrict__ ws, const float* __restrict__ bs) {
    int idx = blockIdx.x * blockDim.x + threadIdx.x;
    int wn = D1 * W2COLS;
    if (idx < wn) {
        int f = idx / W2COLS, c = idx % W2COLS;
        float val = 0.f;
        if (c < 512)        val = wq[f * 512 + c];
        else if (c < 1024)  val = wk[f * 512 + (c - 512)];
        else if (c < 1536)  val = wv[f * 512 + (c - 1024)];
        else if (c < 2048)  val = ws[f * 512 + (c - 1536)];
        else if (c < W2VALID) {
            int t = c - 2048, h = t / 22, g = t % 22;
            float s = 0.f;
            for (int cc = 0; cc < 64; cc++)
                s += wq[f * 512 + h * 64 + cc] * we[g * 512 + h * 64 + cc];
            val = s;
        }
        g_wcat2[f * W2COLS + c] = val;
    } else if (idx < wn + W2COLS) {
        int c = idx - wn;
        float val = 0.f;
        if (c < 512)        val = bq[c];
        else if (c < 1024)  val = bk[c - 512];
        else if (c < 1536)  val = bv[c - 1024];
        else if (c < 2048)  val = bs[c - 1536];
        else if (c < W2VALID) {
            int t = c - 2048, h = t / 22, g = t % 22;
            float s = 0.f;
            for (int cc = 0; cc < 64; cc++)
                s += bq[h * 64 + cc] * we[g * 512 + h * 64 + cc];
            val = s;
        }
        g_bcat2[c] = val;
    }
}

// ---------------- layer1 node GEMM: x[N,22] @ Wcat1[22,1200] -----------------
__global__ void __launch_bounds__(256) k_gemm1(const float* __restrict__ x) {
    __shared__ float xs[FINN][128];
    __shared__ float ws[FINN][128];
    int m0 = blockIdx.x * 128;
    int c0 = blockIdx.y * 128;
    int t = threadIdx.x;
    for (int i = t; i < 128 * FINN; i += 256) {
        int n = i / FINN, f = i % FINN;
        xs[f][n] = (m0 + n < NN) ? x[(m0 + n) * FINN + f] : 0.f;
    }
    for (int i = t; i < FINN * 128; i += 256) {
        int f = i / 128, cc = i % 128;
        ws[f][cc] = (c0 + cc < W1COLS) ? g_wcat1[f * W1COLS + c0 + cc] : 0.f;
    }
    __syncthreads();
    int tr = t >> 4, tc = t & 15;
    float acc[8][8];
#pragma unroll
    for (int i = 0; i < 8; i++)
#pragma unroll
        for (int j = 0; j < 8; j++) acc[i][j] = 0.f;
#pragma unroll
    for (int f = 0; f < FINN; f++) {
        float a[8], b[8];
        *(float4*)(a)     = *(const float4*)&xs[f][tr * 8];
        *(float4*)(a + 4) = *(const float4*)&xs[f][tr * 8 + 4];
        *(float4*)(b)     = *(const float4*)&ws[f][tc * 8];
        *(float4*)(b + 4) = *(const float4*)&ws[f][tc * 8 + 4];
#pragma unroll
        for (int i = 0; i < 8; i++)
#pragma unroll
            for (int j = 0; j < 8; j++) acc[i][j] += a[i] * b[j];
    }
#pragma unroll
    for (int i = 0; i < 8; i++) {
        int row = m0 + tr * 8 + i;
        if (row >= NN) continue;
#pragma unroll
        for (int j = 0; j < 8; j++) {
            int col = c0 + tc * 8 + j;
            if (col >= W1COLS) continue;
            float v = acc[i][j] + g_bcat1[col];
            if (col < 256)       g_q1[row * D1 + col] = v;
            else if (col < 512)  g_k1[row * D1 + col - 256] = v;
            else if (col < 768)  g_v1[row * D1 + col - 512] = v;
            else if (col < 1024) g_x1[row * D1 + col - 768] = v;
            else                 g_qp1[row * QPW + col - 1024] = v;
        }
    }
}

// ---------------- layer2 node GEMM: x1[N,256] @ Wcat2[256,2304] -------------
__global__ void __launch_bounds__(256) k_gemm2() {
    __shared__ float As[16][132];
    __shared__ float Bs[16][128];
    int m0 = blockIdx.x * 128;
    int c0 = blockIdx.y * 128;
    int t = threadIdx.x;
    int tr = t >> 4, tc = t & 15;
    float acc[8][8];
#pragma unroll
    for (int i = 0; i < 8; i++)
#pragma unroll
        for (int j = 0; j < 8; j++) acc[i][j] = 0.f;

    for (int k0 = 0; k0 < D1; k0 += 16) {
#pragma unroll
        for (int l2 = 0; l2 < 2; l2++) {
            int idx = t + l2 * 256;
            int row = idx >> 2;
            int kk = (idx & 3) * 4;
            float4 v = make_float4(0.f, 0.f, 0.f, 0.f);
            if (m0 + row < NN) v = *(const float4*)&g_x1[(m0 + row) * D1 + k0 + kk];
            As[kk][row] = v.x; As[kk + 1][row] = v.y;
            As[kk + 2][row] = v.z; As[kk + 3][row] = v.w;
        }
#pragma unroll
        for (int l2 = 0; l2 < 2; l2++) {
            int idx = t + l2 * 256;
            int r = idx >> 5;
            int c4 = idx & 31;
            *(float4*)&Bs[r][c4 * 4] = *(const float4*)&g_wcat2[(k0 + r) * W2COLS + c0 + c4 * 4];
        }
        __syncthreads();
#pragma unroll
        for (int k = 0; k < 16; k++) {
            float a[8], b[8];
            *(float4*)(a)     = *(const float4*)&As[k][tr * 8];
            *(float4*)(a + 4) = *(const float4*)&As[k][tr * 8 + 4];
            *(float4*)(b)     = *(const float4*)&Bs[k][tc * 8];
            *(float4*)(b + 4) = *(const float4*)&Bs[k][tc * 8 + 4];
#pragma unroll
            for (int i = 0; i < 8; i++)
#pragma unroll
                for (int j = 0; j < 8; j++) acc[i][j] += a[i] * b[j];
        }
        __syncthreads();
    }
#pragma unroll
    for (int i = 0; i < 8; i++) {
        int row = m0 + tr * 8 + i;
        if (row >= NN) continue;
#pragma unroll
        for (int j = 0; j < 8; j++) {
            int col = c0 + tc * 8 + j;
            if (col >= W2VALID) continue;
            float v = acc[i][j] + g_bcat2[col];
            if (col < 512)       g_q2[row * D2 + col] = v;
            else if (col < 1024) g_k2[row * D2 + col - 512] = v;
            else if (col < 1536) g_v2[row * D2 + col - 1024] = v;
            else if (col < 2048) g_x2[row * D2 + col - 1536] = v;
            else                 g_qp2[row * QPW + col - 2048] = v;
        }
    }
}

// ---------------- attention alpha pass (per dst block, online softmax) ------
template <int LAYER>
__global__ void __launch_bounds__(128) k_alpha(const float* __restrict__ attr) {
    constexpr int C = (LAYER == 1) ? 32 : 64;
    constexpr int D = 8 * C;
    constexpr int VPT = D / 128;
    const float* kbuf  = (LAYER == 1) ? g_k1 : g_k2;
    const float* qbuf  = (LAYER == 1) ? g_q1 : g_q2;
    const float* qpbuf = (LAYER == 1) ? g_qp1 : g_qp2;
    const float scale = (LAYER == 1) ? 0.17677669529663687f : 0.125f;

    int dst = blockIdx.x;
    int e0 = g_off[dst], e1v = g_off[dst + 1];
    int deg = e1v - e0;
    if (deg == 0) return;

    int w = threadIdx.x >> 5, l = threadIdx.x & 31;
    int cbase = w * 2 * C;

    float qreg[VPT];
#pragma unroll
    for (int j = 0; j < VPT; j++) qreg[j] = qbuf[dst * D + cbase + j * 32 + l];
    float qpA = 0.f, qpB = 0.f;
    if (l < 22) {
        qpA = qpbuf[dst * QPW + (2 * w) * 22 + l];
        qpB = qpbuf[dst * QPW + (2 * w + 1) * 22 + l];
    }

    __shared__ float sAl[SCAP * 8];
    float mA = -1e30f, mB = -1e30f, sA = 0.f, sB = 0.f;

    for (int i = 0; i < deg; i++) {
        int pos = e0 + i;
        int srcn = g_csrc[pos];
        int eid = g_ceid[pos];
        float tA = 0.f, tB = 0.f;
#pragma unroll
        for (int j = 0; j < VPT; j++) {
            float kv = kbuf[srcn * D + cbase + j * 32 + l];
            float p = qreg[j] * kv;
            if (j < VPT / 2) tA += p; else tB += p;
        }
        if (l < 22) {
            float a = attr[eid * EDIM + l];
            tA += a * qpA;
            tB += a * qpB;
        }
#pragma unroll
        for (int o = 16; o; o >>= 1) {
            tA += __shfl_xor_sync(0xffffffffu, tA, o);
            tB += __shfl_xor_sync(0xffffffffu, tB, o);
        }
        float aA = tA * scale, aB = tB * scale;
        float m2;
        m2 = fmaxf(mA, aA); sA = sA * expf(mA - m2) + expf(aA - m2); mA = m2;
        m2 = fmaxf(mB, aB); sB = sB * expf(mB - m2) + expf(aB - m2); mB = m2;
        if (l == 0 && i < SCAP) {
            sAl[i * 8 + 2 * w]     = aA;
            sAl[i * 8 + 2 * w + 1] = aB;
        }
    }
    __syncwarp();
    float invA = 1.f / (sA + 1e-16f);
    float invB = 1.f / (sB + 1e-16f);
    int lim = (deg < SCAP) ? deg : SCAP;
    for (int i = l; i < lim; i += 32) {
        int pos = e0 + i;
        g_alpha[pos * 8 + 2 * w]     = expf(sAl[i * 8 + 2 * w] - mA) * invA;
        g_alpha[pos * 8 + 2 * w + 1] = expf(sAl[i * 8 + 2 * w + 1] - mB) * invB;
    }
    // overflow fallback (deg > SCAP): recompute alpha
    for (int i = SCAP; i < deg; i++) {
        int pos = e0 + i;
        int srcn = g_csrc[pos];
        int eid = g_ceid[pos];
        float tA = 0.f, tB = 0.f;
#pragma unroll
        for (int j = 0; j < VPT; j++) {
            float kv = kbuf[srcn * D + cbase + j * 32 + l];
            float p = qreg[j] * kv;
            if (j < VPT / 2) tA += p; else tB += p;
        }
        if (l < 22) {
            float a = attr[eid * EDIM + l];
            tA += a * qpA;
            tB += a * qpB;
        }
#pragma unroll
        for (int o = 16; o; o >>= 1) {
            tA += __shfl_xor_sync(0xffffffffu, tA, o);
            tB += __shfl_xor_sync(0xffffffffu, tB, o);
        }
        if (l == 0) {
            g_alpha[pos * 8 + 2 * w]     = expf(tA * scale - mA) * invA;
            g_alpha[pos * 8 + 2 * w + 1] = expf(tB * scale - mB) * invB;
        }
    }
}

// ---------------- message pass + skip + attr-message + relu ----------------
template <int LAYER>
__global__ void __launch_bounds__(128) k_msg(const float* __restrict__ attr,
                                             const float* __restrict__ we) {
    constexpr int C = (LAYER == 1) ? 32 : 64;
    constexpr int D = 8 * C;
    constexpr int VPT = D / 128;
    const float* vbuf = (LAYER == 1) ? g_v1 : g_v2;
    float* outbuf     = (LAYER == 1) ? g_x1 : g_x2;   // pre-initialized with skip

    int dst = blockIdx.x;
    int e0 = g_off[dst], e1v = g_off[dst + 1];
    int deg = e1v - e0;
    int w = threadIdx.x >> 5, l = threadIdx.x & 31;
    int cbase = w * 2 * C;

    float acc[VPT];
#pragma unroll
    for (int j = 0; j < VPT; j++) acc[j] = 0.f;
    float aaA = 0.f, aaB = 0.f;

    for (int i = 0; i < deg; i++) {
        int pos = e0 + i;
        int srcn = g_csrc[pos];
        int eid = g_ceid[pos];
        float aA = g_alpha[pos * 8 + 2 * w];
        float aB = g_alpha[pos * 8 + 2 * w + 1];
#pragma unroll
        for (int j = 0; j < VPT; j++) {
            float vv = vbuf[srcn * D + cbase + j * 32 + l];
            acc[j] += ((j < VPT / 2) ? aA : aB) * vv;
        }
        if (l < 22) {
            float a = attr[eid * EDIM + l];
            aaA += aA * a;
            aaB += aB * a;
        }
    }
    // attr-message: out_h += (sum_e a_eh * attr_e) @ We_h
    float extra[VPT];
#pragma unroll
    for (int j = 0; j < VPT; j++) extra[j] = 0.f;
    for (int g = 0; g < 22; g++) {
        float gA = __shfl_sync(0xffffffffu, aaA, g);
        float gB = __shfl_sync(0xffffffffu, aaB, g);
#pragma unroll
        for (int j = 0; j < VPT; j++) {
            float wv = we[g * D + cbase + j * 32 + l];
            extra[j] += ((j < VPT / 2) ? gA : gB) * wv;
        }
    }
#pragma unroll
    for (int j = 0; j < VPT; j++) {
        int idx = dst * D + cbase + j * 32 + l;
        float v = outbuf[idx] + acc[j] + extra[j];
        outbuf[idx] = fmaxf(v, 0.f);
    }
}

// ---------------- final: sigmoid(concat(x1,x2) @ w_out + b) -----------------
__global__ void __launch_bounds__(128) k_final(const float* __restrict__ wout,
                                               const float* __restrict__ bout,
                                               float* __restrict__ out) {
    int n = blockIdx.x * 4 + (threadIdx.x >> 5);
    if (n >= NN) return;
    int l = threadIdx.x & 31;
    float s = 0.f;
#pragma unroll
    for (int j = 0; j < 8; j++) {
        int c = l + j * 32;
        s += g_x1[n * D1 + c] * wout[c];
    }
#pragma unroll
    for (int j = 0; j < 16; j++) {
        int c = l + j * 32;
        s += g_x2[n * D2 + c] * wout[256 + c];
    }
#pragma unroll
    for (int o = 16; o; o >>= 1) s += __shfl_xor_sync(0xffffffffu, s, o);
    if (l == 0) out[n] = 1.f / (1.f + expf(-(s + bout[0])));
}

// ---------------- launch ----------------------------------------------------
extern "C" void kernel_launch(void* const* d_in, const int* in_sizes, int n_in,
                              void* d_out, int out_size) {
    const float* x  = (const float*)d_in[0];
    const int*   ei = (const int*)d_in[1];   // int32 OR int64 (detected on device)
    const float* ea = (const float*)d_in[2];
    const float* w1_q = (const float*)d_in[3];  const float* b1_q = (const float*)d_in[4];
    const float* w1_k = (const float*)d_in[5];  const float* b1_k = (const float*)d_in[6];
    const float* w1_v = (const float*)d_in[7];  const float* b1_v = (const float*)d_in[8];
    const float* w1_e = (const float*)d_in[9];
    const float* w1_s = (const float*)d_in[10]; const float* b1_s = (const float*)d_in[11];
    const float* w2_q = (const float*)d_in[12]; const float* b2_q = (const float*)d_in[13];
    const float* w2_k = (const float*)d_in[14]; const float* b2_k = (const float*)d_in[15];
    const float* w2_v = (const float*)d_in[16]; const float* b2_v = (const float*)d_in[17];
    const float* w2_e = (const float*)d_in[18];
    const float* w2_s = (const float*)d_in[19]; const float* b2_s = (const float*)d_in[20];
    const float* w_out = (const float*)d_in[21];
    const float* b_out = (const float*)d_in[22];
    float* out = (float*)d_out;

    // dtype probe + CSR build (shared by both layers)
    k_detect<<<1, 32>>>(ei);
    k_zero_counters<<<(NN + 255) / 256, 256>>>();
    k_hist<<<(EE + 255) / 256, 256>>>(ei);
    k_scan<<<1, 1024>>>();
    k_scatter<<<(EE + 255) / 256, 256>>>(ei);

    // layer 1
    k_wcat1<<<(FINN * W1COLS + W1COLS + 255) / 256, 256>>>(w1_q, b1_q, w1_k, b1_k,
                                                           w1_v, b1_v, w1_e, w1_s, b1_s);
    {
        dim3 g((NN + 127) / 128, (W1COLS + 127) / 128);
        k_gemm1<<<g, 256>>>(x);
    }
    k_alpha<1><<<NN, 128>>>(ea);
    k_msg<1><<<NN, 128>>>(ea, w1_e);

    // layer 2
    k_wcat2<<<(D1 * W2COLS + W2COLS + 255) / 256, 256>>>(w2_q, b2_q, w2_k, b2_k,
                                                         w2_v, b2_v, w2_e, w2_s, b2_s);
    {
        dim3 g((NN + 127) / 128, W2COLS / 128);
        k_gemm2<<<g, 256>>>();
    }
    k_alpha<2><<<NN, 128>>>(ea);
    k_msg<2><<<NN, 128>>>(ea, w2_e);

    // output head
    k_final<<<(NN + 3) / 4, 128>>>(w_out, b_out, out);
}

// round 4
// speedup vs baseline: 1.5227x; 1.5227x over previous
#include <cuda_runtime.h>
#include <math.h>

#define NN   50000
#define EE   400000
#define FINN 22
#define EDIM 22
#define HH   8
#define D1   256
#define D2   512
#define QPW  176    /* 8 heads * 22 attr dims */

#define W1COLS 1200    /* 4*256 + 176 */
#define W2COLS 2304    /* 4*512 + 176, padded to 18*128 */
#define W2VALID 2224

#define SCAP 256       /* smem alpha capacity per dst */
#define SCB  49        /* ceil(NN/1024) scan blocks */

// ---------------- scratch (device globals; no allocations allowed) ----------
__device__ float g_q1[NN * D1];
__device__ float g_k1[NN * D1];
__device__ float g_v1[NN * D1];
__device__ float g_x1[NN * D1];
__device__ float g_qp1[NN * QPW];
__device__ float g_q2[NN * D2];
__device__ float g_k2[NN * D2];
__device__ float g_v2[NN * D2];
__device__ float g_x2[NN * D2];
__device__ float g_qp2[NN * QPW];
__device__ float g_alpha[EE * HH];
__device__ int   g_deg[NN];
__device__ int   g_cur[NN];
__device__ int   g_off[NN + 1];
__device__ int   g_csrc[EE];
__device__ int   g_ceid[EE];
__device__ float g_wcat1[FINN * W1COLS];
__device__ float g_bcat1[W1COLS];
__device__ float g_wcat2[D1 * W2COLS];
__device__ float g_bcat2[W2COLS];
__device__ int   g_is64;
__device__ int   g_bsum[SCB];
__device__ int   g_bbase[SCB];

// ---------------- edge_index dtype detection (int32 vs int64) ---------------
__global__ void k_detect(const int* __restrict__ ei) {
    int l = threadIdx.x;
    int nz = 0;
    for (int i = l; i < 1024; i += 32) nz |= (ei[2 * i + 1] != 0);
    unsigned m = __ballot_sync(0xffffffffu, nz);
    if (l == 0) g_is64 = (m == 0);
}

__device__ __forceinline__ int ld_src(const int* __restrict__ ei, int e) {
    return g_is64 ? ei[2 * e] : ei[e];
}
__device__ __forceinline__ int ld_dst(const int* __restrict__ ei, int e) {
    return g_is64 ? ei[2 * (EE + e)] : ei[EE + e];
}

// ---------------- CSR build ----------------
__global__ void k_zero_counters() {
    int i = blockIdx.x * blockDim.x + threadIdx.x;
    if (i < NN) { g_deg[i] = 0; g_cur[i] = 0; }
}

__global__ void k_hist(const int* __restrict__ ei) {
    int e = blockIdx.x * blockDim.x + threadIdx.x;
    if (e < EE) atomicAdd(&g_deg[ld_dst(ei, e)], 1);
}

// 3-phase parallel scan of g_deg into g_off (exclusive, g_off[0]=0)
__global__ void k_scan1() {   // grid=SCB, 1024 threads
    __shared__ int sm[1024];
    int b = blockIdx.x;
    int i = b * 1024 + threadIdx.x;
    int v = (i < NN) ? g_deg[i] : 0;
    sm[threadIdx.x] = v;
    __syncthreads();
    for (int off = 1; off < 1024; off <<= 1) {
        int t = 0;
        if (threadIdx.x >= off) t = sm[threadIdx.x - off];
        __syncthreads();
        if (threadIdx.x >= off) sm[threadIdx.x] += t;
        __syncthreads();
    }
    if (i < NN) g_off[i + 1] = sm[threadIdx.x];
    if (threadIdx.x == 1023) g_bsum[b] = sm[1023];
}
__global__ void k_scan2() {
    if (threadIdx.x == 0) {
        int run = 0;
        for (int b = 0; b < SCB; b++) { g_bbase[b] = run; run += g_bsum[b]; }
        g_off[0] = 0;
    }
}
__global__ void k_scan3() {
    int i = blockIdx.x * blockDim.x + threadIdx.x;
    if (i < NN) g_off[i + 1] += g_bbase[i >> 10];
}

__global__ void k_scatter(const int* __restrict__ ei) {
    int e = blockIdx.x * blockDim.x + threadIdx.x;
    if (e < EE) {
        int src = ld_src(ei, e);
        int dst = ld_dst(ei, e);
        int pos = g_off[dst] + atomicAdd(&g_cur[dst], 1);
        g_csrc[pos] = src;
        g_ceid[pos] = e;
    }
}

// ---------------- weight concat builders (fold qproj = (x@Wq+b)@We_h^T) ----
__global__ void k_wcat1(const float* __restrict__ wq, const float* __restrict__ bq,
                        const float* __restrict__ wk, const float* __restrict__ bk,
                        const float* __restrict__ wv, const float* __restrict__ bv,
                        const float* __restrict__ we,
                        const float* __restrict__ ws, const float* __restrict__ bs) {
    int idx = blockIdx.x * blockDim.x + threadIdx.x;
    int wn = FINN * W1COLS;
    if (idx < wn) {
        int f = idx / W1COLS, c = idx % W1COLS;
        float val;
        if (c < 256)       val = wq[f * 256 + c];
        else if (c < 512)  val = wk[f * 256 + (c - 256)];
        else if (c < 768)  val = wv[f * 256 + (c - 512)];
        else if (c < 1024) val = ws[f * 256 + (c - 768)];
        else {
            int t = c - 1024, h = t / 22, g = t % 22;
            float s = 0.f;
            for (int cc = 0; cc < 32; cc++)
                s += wq[f * 256 + h * 32 + cc] * we[g * 256 + h * 32 + cc];
            val = s;
        }
        g_wcat1[f * W1COLS + c] = val;
    } else if (idx < wn + W1COLS) {
        int c = idx - wn;
        float val;
        if (c < 256)       val = bq[c];
        else if (c < 512)  val = bk[c - 256];
        else if (c < 768)  val = bv[c - 512];
        else if (c < 1024) val = bs[c - 768];
        else {
            int t = c - 1024, h = t / 22, g = t % 22;
            float s = 0.f;
            for (int cc = 0; cc < 32; cc++)
                s += bq[h * 32 + cc] * we[g * 256 + h * 32 + cc];
            val = s;
        }
        g_bcat1[c] = val;
    }
}

__global__ void k_wcat2(const float* __restrict__ wq, const float* __restrict__ bq,
                        const float* __restrict__ wk, const float* __restrict__ bk,
                        const float* __restrict__ wv, const float* __restrict__ bv,
                        const float* __restrict__ we,
                        const float* __restrict__ ws, const float* __restrict__ bs) {
    int idx = blockIdx.x * blockDim.x + threadIdx.x;
    int wn = D1 * W2COLS;
    if (idx < wn) {
        int f = idx / W2COLS, c = idx % W2COLS;
        float val = 0.f;
        if (c < 512)        val = wq[f * 512 + c];
        else if (c < 1024)  val = wk[f * 512 + (c - 512)];
        else if (c < 1536)  val = wv[f * 512 + (c - 1024)];
        else if (c < 2048)  val = ws[f * 512 + (c - 1536)];
        else if (c < W2VALID) {
            int t = c - 2048, h = t / 22, g = t % 22;
            float s = 0.f;
            for (int cc = 0; cc < 64; cc++)
                s += wq[f * 512 + h * 64 + cc] * we[g * 512 + h * 64 + cc];
            val = s;
        }
        g_wcat2[f * W2COLS + c] = val;
    } else if (idx < wn + W2COLS) {
        int c = idx - wn;
        float val = 0.f;
        if (c < 512)        val = bq[c];
        else if (c < 1024)  val = bk[c - 512];
        else if (c < 1536)  val = bv[c - 1024];
        else if (c < 2048)  val = bs[c - 1536];
        else if (c < W2VALID) {
            int t = c - 2048, h = t / 22, g = t % 22;
            float s = 0.f;
            for (int cc = 0; cc < 64; cc++)
                s += bq[h * 64 + cc] * we[g * 512 + h * 64 + cc];
            val = s;
        }
        g_bcat2[c] = val;
    }
}

// ---------------- layer1 node GEMM: x[N,22] @ Wcat1[22,1200] -----------------
__global__ void __launch_bounds__(256) k_gemm1(const float* __restrict__ x) {
    __shared__ float xs[FINN][128];
    __shared__ float ws[FINN][128];
    int m0 = blockIdx.x * 128;
    int c0 = blockIdx.y * 128;
    int t = threadIdx.x;
    for (int i = t; i < 128 * FINN; i += 256) {
        int n = i / FINN, f = i % FINN;
        xs[f][n] = (m0 + n < NN) ? x[(m0 + n) * FINN + f] : 0.f;
    }
    for (int i = t; i < FINN * 128; i += 256) {
        int f = i / 128, cc = i % 128;
        ws[f][cc] = (c0 + cc < W1COLS) ? g_wcat1[f * W1COLS + c0 + cc] : 0.f;
    }
    __syncthreads();
    int tr = t >> 4, tc = t & 15;
    float acc[8][8];
#pragma unroll
    for (int i = 0; i < 8; i++)
#pragma unroll
        for (int j = 0; j < 8; j++) acc[i][j] = 0.f;
#pragma unroll
    for (int f = 0; f < FINN; f++) {
        float a[8], b[8];
        *(float4*)(a)     = *(const float4*)&xs[f][tr * 8];
        *(float4*)(a + 4) = *(const float4*)&xs[f][tr * 8 + 4];
        *(float4*)(b)     = *(const float4*)&ws[f][tc * 8];
        *(float4*)(b + 4) = *(const float4*)&ws[f][tc * 8 + 4];
#pragma unroll
        for (int i = 0; i < 8; i++)
#pragma unroll
            for (int j = 0; j < 8; j++) acc[i][j] += a[i] * b[j];
    }
#pragma unroll
    for (int i = 0; i < 8; i++) {
        int row = m0 + tr * 8 + i;
        if (row >= NN) continue;
#pragma unroll
        for (int j = 0; j < 8; j++) {
            int col = c0 + tc * 8 + j;
            if (col >= W1COLS) continue;
            float v = acc[i][j] + g_bcat1[col];
            if (col < 256)       g_q1[row * D1 + col] = v;
            else if (col < 512)  g_k1[row * D1 + col - 256] = v;
            else if (col < 768)  g_v1[row * D1 + col - 512] = v;
            else if (col < 1024) g_x1[row * D1 + col - 768] = v;
            else                 g_qp1[row * QPW + col - 1024] = v;
        }
    }
}

// ---------------- layer2 node GEMM on tensor cores (tf32 mma.sync) ----------
__device__ __forceinline__ unsigned f2tf(float f) {
    unsigned r;
    asm("cvt.rna.tf32.f32 %0, %1;" : "=r"(r) : "f"(f));
    return r;
}
__device__ __forceinline__ void mma_tf32(float* c, unsigned a0, unsigned a1,
                                         unsigned a2, unsigned a3,
                                         unsigned b0, unsigned b1) {
    asm volatile("mma.sync.aligned.m16n8k8.row.col.f32.tf32.tf32.f32 "
                 "{%0,%1,%2,%3}, {%4,%5,%6,%7}, {%8,%9}, {%0,%1,%2,%3};"
                 : "+f"(c[0]), "+f"(c[1]), "+f"(c[2]), "+f"(c[3])
                 : "r"(a0), "r"(a1), "r"(a2), "r"(a3), "r"(b0), "r"(b1));
}

__device__ __forceinline__ void store_l2(int row, int col, float v) {
    if (row >= NN || col >= W2VALID) return;
    v += g_bcat2[col];
    if (col < 512)       g_q2[row * D2 + col] = v;
    else if (col < 1024) g_k2[row * D2 + col - 512] = v;
    else if (col < 1536) g_v2[row * D2 + col - 1024] = v;
    else if (col < 2048) g_x2[row * D2 + col - 1536] = v;
    else                 g_qp2[row * QPW + col - 2048] = v;
}

// BM=128, BN=128, BK=32; 8 warps (2x4), warp tile 64x32; m16n8k8 tf32
__global__ void __launch_bounds__(256) k_gemm2_tc() {
    __shared__ float As[128 * 36];   // [m][k], stride 36 (conflict-free frags)
    __shared__ float Bs[32 * 136];   // [k][n], stride 136

    int m0 = blockIdx.x * 128;
    int c0 = blockIdx.y * 128;
    int t = threadIdx.x;
    int w = t >> 5, l = t & 31;
    int wm = (w >> 2) * 64;
    int wn = (w & 3) * 32;
    int gp = l >> 2, tq = l & 3;

    float acc[4][4][4];
#pragma unroll
    for (int a = 0; a < 4; a++)
#pragma unroll
        for (int b = 0; b < 4; b++)
#pragma unroll
            for (int cc = 0; cc < 4; cc++) acc[a][b][cc] = 0.f;

    for (int kc = 0; kc < 8; kc++) {
        // A: 128x32 floats (g_x1 rows), direct copy [m][k]
#pragma unroll
        for (int li = 0; li < 4; li++) {
            int idx = t + li * 256;
            int m = idx >> 3, kq = idx & 7;
            float4 v = make_float4(0.f, 0.f, 0.f, 0.f);
            if (m0 + m < NN)
                v = *(const float4*)&g_x1[(m0 + m) * D1 + kc * 32 + kq * 4];
            *(float4*)&As[m * 36 + kq * 4] = v;
        }
        // B: 32x128 floats, [k][n]
#pragma unroll
        for (int li = 0; li < 4; li++) {
            int idx = t + li * 256;
            int r = idx >> 5, c4 = (idx & 31) * 4;
            *(float4*)&Bs[r * 136 + c4] =
                *(const float4*)&g_wcat2[(kc * 32 + r) * W2COLS + c0 + c4];
        }
        __syncthreads();
#pragma unroll
        for (int kb = 0; kb < 4; kb++) {
            int k0 = kb * 8;
            unsigned af[4][4], bf[4][2];
#pragma unroll
            for (int mt = 0; mt < 4; mt++) {
                int row = wm + mt * 16 + gp;
                af[mt][0] = f2tf(As[row * 36 + k0 + tq]);
                af[mt][1] = f2tf(As[(row + 8) * 36 + k0 + tq]);
                af[mt][2] = f2tf(As[row * 36 + k0 + tq + 4]);
                af[mt][3] = f2tf(As[(row + 8) * 36 + k0 + tq + 4]);
            }
#pragma unroll
            for (int nt = 0; nt < 4; nt++) {
                int col = wn + nt * 8 + gp;
                bf[nt][0] = f2tf(Bs[(k0 + tq) * 136 + col]);
                bf[nt][1] = f2tf(Bs[(k0 + tq + 4) * 136 + col]);
            }
#pragma unroll
            for (int mt = 0; mt < 4; mt++)
#pragma unroll
                for (int nt = 0; nt < 4; nt++)
                    mma_tf32(acc[mt][nt], af[mt][0], af[mt][1], af[mt][2],
                             af[mt][3], bf[nt][0], bf[nt][1]);
        }
        __syncthreads();
    }
    // epilogue
#pragma unroll
    for (int mt = 0; mt < 4; mt++) {
        int r0 = m0 + wm + mt * 16 + gp;
#pragma unroll
        for (int nt = 0; nt < 4; nt++) {
            int cb = c0 + wn + nt * 8 + tq * 2;
            store_l2(r0,     cb,     acc[mt][nt][0]);
            store_l2(r0,     cb + 1, acc[mt][nt][1]);
            store_l2(r0 + 8, cb,     acc[mt][nt][2]);
            store_l2(r0 + 8, cb + 1, acc[mt][nt][3]);
        }
    }
}

// ---------------- attention alpha pass (per dst block, online softmax) ------
template <int LAYER>
__global__ void __launch_bounds__(128) k_alpha(const float* __restrict__ attr) {
    constexpr int C = (LAYER == 1) ? 32 : 64;
    constexpr int D = 8 * C;
    constexpr int VPT = D / 128;
    const float* kbuf  = (LAYER == 1) ? g_k1 : g_k2;
    const float* qbuf  = (LAYER == 1) ? g_q1 : g_q2;
    const float* qpbuf = (LAYER == 1) ? g_qp1 : g_qp2;
    const float scale = (LAYER == 1) ? 0.17677669529663687f : 0.125f;

    int dst = blockIdx.x;
    int e0 = g_off[dst], e1v = g_off[dst + 1];
    int deg = e1v - e0;
    if (deg == 0) return;

    int w = threadIdx.x >> 5, l = threadIdx.x & 31;
    int cbase = w * 2 * C;

    float qreg[VPT];
#pragma unroll
    for (int j = 0; j < VPT; j++) qreg[j] = qbuf[dst * D + cbase + j * 32 + l];
    float qpA = 0.f, qpB = 0.f;
    if (l < 22) {
        qpA = qpbuf[dst * QPW + (2 * w) * 22 + l];
        qpB = qpbuf[dst * QPW + (2 * w + 1) * 22 + l];
    }

    __shared__ float sAl[SCAP * 8];
    float mA = -1e30f, mB = -1e30f, sA = 0.f, sB = 0.f;

    for (int i = 0; i < deg; i++) {
        int pos = e0 + i;
        int srcn = g_csrc[pos];
        int eid = g_ceid[pos];
        float tA = 0.f, tB = 0.f;
#pragma unroll
        for (int j = 0; j < VPT; j++) {
            float kv = kbuf[srcn * D + cbase + j * 32 + l];
            float p = qreg[j] * kv;
            if (j < VPT / 2) tA += p; else tB += p;
        }
        if (l < 22) {
            float a = attr[eid * EDIM + l];
            tA += a * qpA;
            tB += a * qpB;
        }
#pragma unroll
        for (int o = 16; o; o >>= 1) {
            tA += __shfl_xor_sync(0xffffffffu, tA, o);
            tB += __shfl_xor_sync(0xffffffffu, tB, o);
        }
        float aA = tA * scale, aB = tB * scale;
        float m2;
        m2 = fmaxf(mA, aA); sA = sA * expf(mA - m2) + expf(aA - m2); mA = m2;
        m2 = fmaxf(mB, aB); sB = sB * expf(mB - m2) + expf(aB - m2); mB = m2;
        if (l == 0 && i < SCAP) {
            sAl[i * 8 + 2 * w]     = aA;
            sAl[i * 8 + 2 * w + 1] = aB;
        }
    }
    __syncwarp();
    float invA = 1.f / (sA + 1e-16f);
    float invB = 1.f / (sB + 1e-16f);
    int lim = (deg < SCAP) ? deg : SCAP;
    for (int i = l; i < lim; i += 32) {
        int pos = e0 + i;
        g_alpha[pos * 8 + 2 * w]     = expf(sAl[i * 8 + 2 * w] - mA) * invA;
        g_alpha[pos * 8 + 2 * w + 1] = expf(sAl[i * 8 + 2 * w + 1] - mB) * invB;
    }
    for (int i = SCAP; i < deg; i++) {
        int pos = e0 + i;
        int srcn = g_csrc[pos];
        int eid = g_ceid[pos];
        float tA = 0.f, tB = 0.f;
#pragma unroll
        for (int j = 0; j < VPT; j++) {
            float kv = kbuf[srcn * D + cbase + j * 32 + l];
            float p = qreg[j] * kv;
            if (j < VPT / 2) tA += p; else tB += p;
        }
        if (l < 22) {
            float a = attr[eid * EDIM + l];
            tA += a * qpA;
            tB += a * qpB;
        }
#pragma unroll
        for (int o = 16; o; o >>= 1) {
            tA += __shfl_xor_sync(0xffffffffu, tA, o);
            tB += __shfl_xor_sync(0xffffffffu, tB, o);
        }
        if (l == 0) {
            g_alpha[pos * 8 + 2 * w]     = expf(tA * scale - mA) * invA;
            g_alpha[pos * 8 + 2 * w + 1] = expf(tB * scale - mB) * invB;
        }
    }
}

// ---------------- message pass + skip + attr-message + relu ----------------
template <int LAYER>
__global__ void __launch_bounds__(128) k_msg(const float* __restrict__ attr,
                                             const float* __restrict__ we) {
    constexpr int C = (LAYER == 1) ? 32 : 64;
    constexpr int D = 8 * C;
    constexpr int VPT = D / 128;
    const float* vbuf = (LAYER == 1) ? g_v1 : g_v2;
    float* outbuf     = (LAYER == 1) ? g_x1 : g_x2;   // pre-initialized with skip

    int dst = blockIdx.x;
    int e0 = g_off[dst], e1v = g_off[dst + 1];
    int deg = e1v - e0;
    int w = threadIdx.x >> 5, l = threadIdx.x & 31;
    int cbase = w * 2 * C;

    float acc[VPT];
#pragma unroll
    for (int j = 0; j < VPT; j++) acc[j] = 0.f;
    float aaA = 0.f, aaB = 0.f;

    for (int i = 0; i < deg; i++) {
        int pos = e0 + i;
        int srcn = g_csrc[pos];
        int eid = g_ceid[pos];
        float aA = g_alpha[pos * 8 + 2 * w];
        float aB = g_alpha[pos * 8 + 2 * w + 1];
#pragma unroll
        for (int j = 0; j < VPT; j++) {
            float vv = vbuf[srcn * D + cbase + j * 32 + l];
            acc[j] += ((j < VPT / 2) ? aA : aB) * vv;
        }
        if (l < 22) {
            float a = attr[eid * EDIM + l];
            aaA += aA * a;
            aaB += aB * a;
        }
    }
    float extra[VPT];
#pragma unroll
    for (int j = 0; j < VPT; j++) extra[j] = 0.f;
    for (int g = 0; g < 22; g++) {
        float gA = __shfl_sync(0xffffffffu, aaA, g);
        float gB = __shfl_sync(0xffffffffu, aaB, g);
#pragma unroll
        for (int j = 0; j < VPT; j++) {
            float wv = we[g * D + cbase + j * 32 + l];
            extra[j] += ((j < VPT / 2) ? gA : gB) * wv;
        }
    }
#pragma unroll
    for (int j = 0; j < VPT; j++) {
        int idx = dst * D + cbase + j * 32 + l;
        float v = outbuf[idx] + acc[j] + extra[j];
        outbuf[idx] = fmaxf(v, 0.f);
    }
}

// ---------------- final: sigmoid(concat(x1,x2) @ w_out + b) -----------------
__global__ void __launch_bounds__(128) k_final(const float* __restrict__ wout,
                                               const float* __restrict__ bout,
                                               float* __restrict__ out) {
    int n = blockIdx.x * 4 + (threadIdx.x >> 5);
    if (n >= NN) return;
    int l = threadIdx.x & 31;
    float s = 0.f;
#pragma unroll
    for (int j = 0; j < 8; j++) {
        int c = l + j * 32;
        s += g_x1[n * D1 + c] * wout[c];
    }
#pragma unroll
    for (int j = 0; j < 16; j++) {
        int c = l + j * 32;
        s += g_x2[n * D2 + c] * wout[256 + c];
    }
#pragma unroll
    for (int o = 16; o; o >>= 1) s += __shfl_xor_sync(0xffffffffu, s, o);
    if (l == 0) out[n] = 1.f / (1.f + expf(-(s + bout[0])));
}

// ---------------- launch ----------------------------------------------------
extern "C" void kernel_launch(void* const* d_in, const int* in_sizes, int n_in,
                              void* d_out, int out_size) {
    const float* x  = (const float*)d_in[0];
    const int*   ei = (const int*)d_in[1];   // int32 OR int64 (device-detected)
    const float* ea = (const float*)d_in[2];
    const float* w1_q = (const float*)d_in[3];  const float* b1_q = (const float*)d_in[4];
    const float* w1_k = (const float*)d_in[5];  const float* b1_k = (const float*)d_in[6];
    const float* w1_v = (const float*)d_in[7];  const float* b1_v = (const float*)d_in[8];
    const float* w1_e = (const float*)d_in[9];
    const float* w1_s = (const float*)d_in[10]; const float* b1_s = (const float*)d_in[11];
    const float* w2_q = (const float*)d_in[12]; const float* b2_q = (const float*)d_in[13];
    const float* w2_k = (const float*)d_in[14]; const float* b2_k = (const float*)d_in[15];
    const float* w2_v = (const float*)d_in[16]; const float* b2_v = (const float*)d_in[17];
    const float* w2_e = (const float*)d_in[18];
    const float* w2_s = (const float*)d_in[19]; const float* b2_s = (const float*)d_in[20];
    const float* w_out = (const float*)d_in[21];
    const float* b_out = (const float*)d_in[22];
    float* out = (float*)d_out;

    // dtype probe + CSR build (shared by both layers)
    k_detect<<<1, 32>>>(ei);
    k_zero_counters<<<(NN + 255) / 256, 256>>>();
    k_hist<<<(EE + 255) / 256, 256>>>(ei);
    k_scan1<<<SCB, 1024>>>();
    k_scan2<<<1, 64>>>();
    k_scan3<<<(NN + 255) / 256, 256>>>();
    k_scatter<<<(EE + 255) / 256, 256>>>(ei);

    // layer 1
    k_wcat1<<<(FINN * W1COLS + W1COLS + 255) / 256, 256>>>(w1_q, b1_q, w1_k, b1_k,
                                                           w1_v, b1_v, w1_e, w1_s, b1_s);
    {
        dim3 g((NN + 127) / 128, (W1COLS + 127) / 128);
        k_gemm1<<<g, 256>>>(x);
    }
    k_alpha<1><<<NN, 128>>>(ea);
    k_msg<1><<<NN, 128>>>(ea, w1_e);

    // layer 2 (tensor-core GEMM)
    k_wcat2<<<(D1 * W2COLS + W2COLS + 255) / 256, 256>>>(w2_q, b2_q, w2_k, b2_k,
                                                         w2_v, b2_v, w2_e, w2_s, b2_s);
    {
        dim3 g((NN + 127) / 128, W2COLS / 128);
        k_gemm2_tc<<<g, 256>>>();
    }
    k_alpha<2><<<NN, 128>>>(ea);
    k_msg<2><<<NN, 128>>>(ea, w2_e);

    // output head
    k_final<<<(NN + 3) / 4, 128>>>(w_out, b_out, out);
}

// round 5
// speedup vs baseline: 1.6709x; 1.0974x over previous
#include <cuda_runtime.h>
#include <math.h>

#define NN   50000
#define EE   400000
#define FINN 22
#define EDIM 22
#define HH   8
#define D1   256
#define D2   512
#define QPW  176    /* 8 heads * 22 attr dims */

#define W1COLS 1200    /* 4*256 + 176 */
#define W2COLS 2304    /* 4*512 + 176, padded to 18*128 */
#define W2VALID 2224

#define SCAP 256       /* smem alpha capacity per dst */
#define SCB  49        /* ceil(NN/1024) scan blocks */

// ---------------- scratch (device globals; no allocations allowed) ----------
__device__ float g_q1[NN * D1];
__device__ float g_k1[NN * D1];
__device__ float g_v1[NN * D1];
__device__ float g_x1[NN * D1];
__device__ float g_qp1[NN * QPW];
__device__ float g_q2[NN * D2];
__device__ float g_k2[NN * D2];
__device__ float g_v2[NN * D2];
__device__ float g_x2[NN * D2];
__device__ float g_qp2[NN * QPW];
__device__ int   g_deg[NN];
__device__ int   g_cur[NN];
__device__ int   g_off[NN + 1];
__device__ int   g_csrc[EE];
__device__ int   g_ceid[EE];
__device__ float g_wcat1[FINN * W1COLS];
__device__ float g_bcat1[W1COLS];
__device__ float g_wcat2[D1 * W2COLS];
__device__ float g_bcat2[W2COLS];
__device__ int   g_is64;
__device__ int   g_bsum[SCB];
__device__ int   g_bbase[SCB];

// ---------------- edge_index dtype detection (int32 vs int64) ---------------
__global__ void k_detect(const int* __restrict__ ei) {
    int l = threadIdx.x;
    int nz = 0;
    for (int i = l; i < 1024; i += 32) nz |= (ei[2 * i + 1] != 0);
    unsigned m = __ballot_sync(0xffffffffu, nz);
    if (l == 0) g_is64 = (m == 0);
}

__device__ __forceinline__ int ld_src(const int* __restrict__ ei, int e) {
    return g_is64 ? ei[2 * e] : ei[e];
}
__device__ __forceinline__ int ld_dst(const int* __restrict__ ei, int e) {
    return g_is64 ? ei[2 * (EE + e)] : ei[EE + e];
}

// ---------------- CSR build ----------------
__global__ void k_zero_counters() {
    int i = blockIdx.x * blockDim.x + threadIdx.x;
    if (i < NN) { g_deg[i] = 0; g_cur[i] = 0; }
}

__global__ void k_hist(const int* __restrict__ ei) {
    int e = blockIdx.x * blockDim.x + threadIdx.x;
    if (e < EE) atomicAdd(&g_deg[ld_dst(ei, e)], 1);
}

__global__ void k_scan1() {
    __shared__ int sm[1024];
    int b = blockIdx.x;
    int i = b * 1024 + threadIdx.x;
    int v = (i < NN) ? g_deg[i] : 0;
    sm[threadIdx.x] = v;
    __syncthreads();
    for (int off = 1; off < 1024; off <<= 1) {
        int t = 0;
        if (threadIdx.x >= off) t = sm[threadIdx.x - off];
        __syncthreads();
        if (threadIdx.x >= off) sm[threadIdx.x] += t;
        __syncthreads();
    }
    if (i < NN) g_off[i + 1] = sm[threadIdx.x];
    if (threadIdx.x == 1023) g_bsum[b] = sm[1023];
}
__global__ void k_scan2() {
    if (threadIdx.x == 0) {
        int run = 0;
        for (int b = 0; b < SCB; b++) { g_bbase[b] = run; run += g_bsum[b]; }
        g_off[0] = 0;
    }
}
__global__ void k_scan3() {
    int i = blockIdx.x * blockDim.x + threadIdx.x;
    if (i < NN) g_off[i + 1] += g_bbase[i >> 10];
}

__global__ void k_scatter(const int* __restrict__ ei) {
    int e = blockIdx.x * blockDim.x + threadIdx.x;
    if (e < EE) {
        int src = ld_src(ei, e);
        int dst = ld_dst(ei, e);
        int pos = g_off[dst] + atomicAdd(&g_cur[dst], 1);
        g_csrc[pos] = src;
        g_ceid[pos] = e;
    }
}

// ---------------- weight concat builders (fold qproj = (x@Wq+b)@We_h^T) ----
__global__ void k_wcat1(const float* __restrict__ wq, const float* __restrict__ bq,
                        const float* __restrict__ wk, const float* __restrict__ bk,
                        const float* __restrict__ wv, const float* __restrict__ bv,
                        const float* __restrict__ we,
                        const float* __restrict__ ws, const float* __restrict__ bs) {
    int idx = blockIdx.x * blockDim.x + threadIdx.x;
    int wn = FINN * W1COLS;
    if (idx < wn) {
        int f = idx / W1COLS, c = idx % W1COLS;
        float val;
        if (c < 256)       val = wq[f * 256 + c];
        else if (c < 512)  val = wk[f * 256 + (c - 256)];
        else if (c < 768)  val = wv[f * 256 + (c - 512)];
        else if (c < 1024) val = ws[f * 256 + (c - 768)];
        else {
            int t = c - 1024, h = t / 22, g = t % 22;
            float s = 0.f;
            for (int cc = 0; cc < 32; cc++)
                s += wq[f * 256 + h * 32 + cc] * we[g * 256 + h * 32 + cc];
            val = s;
        }
        g_wcat1[f * W1COLS + c] = val;
    } else if (idx < wn + W1COLS) {
        int c = idx - wn;
        float val;
        if (c < 256)       val = bq[c];
        else if (c < 512)  val = bk[c - 256];
        else if (c < 768)  val = bv[c - 512];
        else if (c < 1024) val = bs[c - 768];
        else {
            int t = c - 1024, h = t / 22, g = t % 22;
            float s = 0.f;
            for (int cc = 0; cc < 32; cc++)
                s += bq[h * 32 + cc] * we[g * 256 + h * 32 + cc];
            val = s;
        }
        g_bcat1[c] = val;
    }
}

__global__ void k_wcat2(const float* __restrict__ wq, const float* __restrict__ bq,
                        const float* __restrict__ wk, const float* __restrict__ bk,
                        const float* __restrict__ wv, const float* __restrict__ bv,
                        const float* __restrict__ we,
                        const float* __restrict__ ws, const float* __restrict__ bs) {
    int idx = blockIdx.x * blockDim.x + threadIdx.x;
    int wn = D1 * W2COLS;
    if (idx < wn) {
        int f = idx / W2COLS, c = idx % W2COLS;
        float val = 0.f;
        if (c < 512)        val = wq[f * 512 + c];
        else if (c < 1024)  val = wk[f * 512 + (c - 512)];
        else if (c < 1536)  val = wv[f * 512 + (c - 1024)];
        else if (c < 2048)  val = ws[f * 512 + (c - 1536)];
        else if (c < W2VALID) {
            int t = c - 2048, h = t / 22, g = t % 22;
            float s = 0.f;
            for (int cc = 0; cc < 64; cc++)
                s += wq[f * 512 + h * 64 + cc] * we[g * 512 + h * 64 + cc];
            val = s;
        }
        g_wcat2[f * W2COLS + c] = val;
    } else if (idx < wn + W2COLS) {
        int c = idx - wn;
        float val = 0.f;
        if (c < 512)        val = bq[c];
        else if (c < 1024)  val = bk[c - 512];
        else if (c < 1536)  val = bv[c - 1024];
        else if (c < 2048)  val = bs[c - 1536];
        else if (c < W2VALID) {
            int t = c - 2048, h = t / 22, g = t % 22;
            float s = 0.f;
            for (int cc = 0; cc < 64; cc++)
                s += bq[h * 64 + cc] * we[g * 512 + h * 64 + cc];
            val = s;
        }
        g_bcat2[c] = val;
    }
}

// ---------------- layer1 node GEMM: x[N,22] @ Wcat1[22,1200] -----------------
__global__ void __launch_bounds__(256) k_gemm1(const float* __restrict__ x) {
    __shared__ float xs[FINN][128];
    __shared__ float ws[FINN][128];
    int m0 = blockIdx.x * 128;
    int c0 = blockIdx.y * 128;
    int t = threadIdx.x;
    for (int i = t; i < 128 * FINN; i += 256) {
        int n = i / FINN, f = i % FINN;
        xs[f][n] = (m0 + n < NN) ? x[(m0 + n) * FINN + f] : 0.f;
    }
    for (int i = t; i < FINN * 128; i += 256) {
        int f = i / 128, cc = i % 128;
        ws[f][cc] = (c0 + cc < W1COLS) ? g_wcat1[f * W1COLS + c0 + cc] : 0.f;
    }
    __syncthreads();
    int tr = t >> 4, tc = t & 15;
    float acc[8][8];
#pragma unroll
    for (int i = 0; i < 8; i++)
#pragma unroll
        for (int j = 0; j < 8; j++) acc[i][j] = 0.f;
#pragma unroll
    for (int f = 0; f < FINN; f++) {
        float a[8], b[8];
        *(float4*)(a)     = *(const float4*)&xs[f][tr * 8];
        *(float4*)(a + 4) = *(const float4*)&xs[f][tr * 8 + 4];
        *(float4*)(b)     = *(const float4*)&ws[f][tc * 8];
        *(float4*)(b + 4) = *(const float4*)&ws[f][tc * 8 + 4];
#pragma unroll
        for (int i = 0; i < 8; i++)
#pragma unroll
            for (int j = 0; j < 8; j++) acc[i][j] += a[i] * b[j];
    }
#pragma unroll
    for (int i = 0; i < 8; i++) {
        int row = m0 + tr * 8 + i;
        if (row >= NN) continue;
#pragma unroll
        for (int j = 0; j < 8; j++) {
            int col = c0 + tc * 8 + j;
            if (col >= W1COLS) continue;
            float v = acc[i][j] + g_bcat1[col];
            if (col < 256)       g_q1[row * D1 + col] = v;
            else if (col < 512)  g_k1[row * D1 + col - 256] = v;
            else if (col < 768)  g_v1[row * D1 + col - 512] = v;
            else if (col < 1024) g_x1[row * D1 + col - 768] = v;
            else                 g_qp1[row * QPW + col - 1024] = v;
        }
    }
}

// ---------------- layer2 GEMM: tf32 mma.sync + cp.async double buffering ----
__device__ __forceinline__ void mma_tf32(float* c, unsigned a0, unsigned a1,
                                         unsigned a2, unsigned a3,
                                         unsigned b0, unsigned b1) {
    asm volatile("mma.sync.aligned.m16n8k8.row.col.f32.tf32.tf32.f32 "
                 "{%0,%1,%2,%3}, {%4,%5,%6,%7}, {%8,%9}, {%0,%1,%2,%3};"
                 : "+f"(c[0]), "+f"(c[1]), "+f"(c[2]), "+f"(c[3])
                 : "r"(a0), "r"(a1), "r"(a2), "r"(a3), "r"(b0), "r"(b1));
}

__device__ __forceinline__ void cp16(void* sptr, const void* gptr) {
    unsigned sa = (unsigned)__cvta_generic_to_shared(sptr);
    asm volatile("cp.async.cg.shared.global [%0], [%1], 16;" :: "r"(sa), "l"(gptr));
}

__device__ __forceinline__ void store_l2(int row, int col, float v) {
    if (row >= NN || col >= W2VALID) return;
    v += g_bcat2[col];
    if (col < 512)       g_q2[row * D2 + col] = v;
    else if (col < 1024) g_k2[row * D2 + col - 512] = v;
    else if (col < 1536) g_v2[row * D2 + col - 1024] = v;
    else if (col < 2048) g_x2[row * D2 + col - 1536] = v;
    else                 g_qp2[row * QPW + col - 2048] = v;
}

#define ASTRIDE 36
#define BSTRIDE 136
#define ASZ (128 * ASTRIDE)
#define BSZ (32 * BSTRIDE)
#define G2_SMEM ((2 * ASZ + 2 * BSZ) * 4)

// BM=128, BN=128, BK=32; 8 warps (2x4), warp tile 64x32; m16n8k8 tf32
// fp32 bits fed directly to tf32 mma (HW ignores low 13 mantissa bits).
__global__ void __launch_bounds__(256) k_gemm2_tc() {
    extern __shared__ float sm[];
    float* As[2] = { sm, sm + ASZ };
    float* Bs[2] = { sm + 2 * ASZ, sm + 2 * ASZ + BSZ };

    int m0 = blockIdx.x * 128;
    int c0 = blockIdx.y * 128;
    int t = threadIdx.x;
    int w = t >> 5, l = t & 31;
    int wm = (w >> 2) * 64;
    int wn = (w & 3) * 32;
    int gp = l >> 2, tq = l & 3;

    float acc[4][4][4];
#pragma unroll
    for (int a = 0; a < 4; a++)
#pragma unroll
        for (int b = 0; b < 4; b++)
#pragma unroll
            for (int cc = 0; cc < 4; cc++) acc[a][b][cc] = 0.f;

    auto load_stage = [&](int kc, int s) {
#pragma unroll
        for (int li = 0; li < 4; li++) {
            int idx = t + li * 256;
            int m = idx >> 3, kq = (idx & 7) * 4;
            float* sp = &As[s][m * ASTRIDE + kq];
            if (m0 + m < NN)
                cp16(sp, &g_x1[(m0 + m) * D1 + kc * 32 + kq]);
            else
                *(float4*)sp = make_float4(0.f, 0.f, 0.f, 0.f);
        }
#pragma unroll
        for (int li = 0; li < 4; li++) {
            int idx = t + li * 256;
            int r = idx >> 5, c4 = (idx & 31) * 4;
            cp16(&Bs[s][r * BSTRIDE + c4],
                 &g_wcat2[(kc * 32 + r) * W2COLS + c0 + c4]);
        }
    };

    load_stage(0, 0);
    asm volatile("cp.async.commit_group;");

    for (int kc = 0; kc < 8; kc++) {
        int cur = kc & 1;
        if (kc < 7) {
            load_stage(kc + 1, cur ^ 1);
            asm volatile("cp.async.commit_group;");
            asm volatile("cp.async.wait_group 1;");
        } else {
            asm volatile("cp.async.wait_group 0;");
        }
        __syncthreads();
        const float* A = As[cur];
        const float* B = Bs[cur];
#pragma unroll
        for (int kb = 0; kb < 4; kb++) {
            int k0 = kb * 8;
            unsigned af[4][4], bf[4][2];
#pragma unroll
            for (int mt = 0; mt < 4; mt++) {
                int row = wm + mt * 16 + gp;
                af[mt][0] = __float_as_uint(A[row * ASTRIDE + k0 + tq]);
                af[mt][1] = __float_as_uint(A[(row + 8) * ASTRIDE + k0 + tq]);
                af[mt][2] = __float_as_uint(A[row * ASTRIDE + k0 + tq + 4]);
                af[mt][3] = __float_as_uint(A[(row + 8) * ASTRIDE + k0 + tq + 4]);
            }
#pragma unroll
            for (int nt = 0; nt < 4; nt++) {
                int col = wn + nt * 8 + gp;
                bf[nt][0] = __float_as_uint(B[(k0 + tq) * BSTRIDE + col]);
                bf[nt][1] = __float_as_uint(B[(k0 + tq + 4) * BSTRIDE + col]);
            }
#pragma unroll
            for (int mt = 0; mt < 4; mt++)
#pragma unroll
                for (int nt = 0; nt < 4; nt++)
                    mma_tf32(acc[mt][nt], af[mt][0], af[mt][1], af[mt][2],
                             af[mt][3], bf[nt][0], bf[nt][1]);
        }
        __syncthreads();
    }
#pragma unroll
    for (int mt = 0; mt < 4; mt++) {
        int r0 = m0 + wm + mt * 16 + gp;
#pragma unroll
        for (int nt = 0; nt < 4; nt++) {
            int cb = c0 + wn + nt * 8 + tq * 2;
            store_l2(r0,     cb,     acc[mt][nt][0]);
            store_l2(r0,     cb + 1, acc[mt][nt][1]);
            store_l2(r0 + 8, cb,     acc[mt][nt][2]);
            store_l2(r0 + 8, cb + 1, acc[mt][nt][3]);
        }
    }
}

// ---------------- fused attention: softmax + message + skip + relu ----------
// One block per dst node; warp w owns heads 2w, 2w+1. Alphas staged in smem.
template <int LAYER>
__global__ void __launch_bounds__(128) k_edge(const float* __restrict__ attr,
                                              const float* __restrict__ we) {
    constexpr int C = (LAYER == 1) ? 32 : 64;
    constexpr int D = 8 * C;
    constexpr int VPT = D / 128;
    const float* kbuf  = (LAYER == 1) ? g_k1 : g_k2;
    const float* qbuf  = (LAYER == 1) ? g_q1 : g_q2;
    const float* qpbuf = (LAYER == 1) ? g_qp1 : g_qp2;
    const float* vbuf  = (LAYER == 1) ? g_v1 : g_v2;
    float* outbuf      = (LAYER == 1) ? g_x1 : g_x2;   // pre-seeded with skip
    const float scale = (LAYER == 1) ? 0.17677669529663687f : 0.125f;

    int dst = blockIdx.x;
    int e0 = g_off[dst], e1v = g_off[dst + 1];
    int deg = e1v - e0;

    int w = threadIdx.x >> 5, l = threadIdx.x & 31;
    int cbase = w * 2 * C;

    float qreg[VPT];
#pragma unroll
    for (int j = 0; j < VPT; j++) qreg[j] = qbuf[dst * D + cbase + j * 32 + l];
    float qpA = 0.f, qpB = 0.f;
    if (l < 22) {
        qpA = qpbuf[dst * QPW + (2 * w) * 22 + l];
        qpB = qpbuf[dst * QPW + (2 * w + 1) * 22 + l];
    }

    __shared__ float sAl[SCAP * 8];
    float mA = -1e30f, mB = -1e30f, sA = 0.f, sB = 0.f;

    // ---- phase A: logits + online softmax stats (unrolled by 2) ----
    int i = 0;
    for (; i + 2 <= deg; i += 2) {
        int p0 = e0 + i, p1 = e0 + i + 1;
        int s0 = g_csrc[p0], s1 = g_csrc[p1];
        int id0 = g_ceid[p0], id1 = g_ceid[p1];
        float t0A = 0.f, t0B = 0.f, t1A = 0.f, t1B = 0.f;
#pragma unroll
        for (int j = 0; j < VPT; j++) {
            float k0v = kbuf[s0 * D + cbase + j * 32 + l];
            float k1v = kbuf[s1 * D + cbase + j * 32 + l];
            if (j < VPT / 2) { t0A += qreg[j] * k0v; t1A += qreg[j] * k1v; }
            else             { t0B += qreg[j] * k0v; t1B += qreg[j] * k1v; }
        }
        if (l < 22) {
            float a0 = attr[id0 * EDIM + l], a1 = attr[id1 * EDIM + l];
            t0A += a0 * qpA; t0B += a0 * qpB;
            t1A += a1 * qpA; t1B += a1 * qpB;
        }
#pragma unroll
        for (int o = 16; o; o >>= 1) {
            t0A += __shfl_xor_sync(0xffffffffu, t0A, o);
            t0B += __shfl_xor_sync(0xffffffffu, t0B, o);
            t1A += __shfl_xor_sync(0xffffffffu, t1A, o);
            t1B += __shfl_xor_sync(0xffffffffu, t1B, o);
        }
        float a0A = t0A * scale, a0B = t0B * scale;
        float a1A = t1A * scale, a1B = t1B * scale;
        float m2;
        m2 = fmaxf(mA, a0A); sA = sA * __expf(mA - m2) + __expf(a0A - m2); mA = m2;
        m2 = fmaxf(mA, a1A); sA = sA * __expf(mA - m2) + __expf(a1A - m2); mA = m2;
        m2 = fmaxf(mB, a0B); sB = sB * __expf(mB - m2) + __expf(a0B - m2); mB = m2;
        m2 = fmaxf(mB, a1B); sB = sB * __expf(mB - m2) + __expf(a1B - m2); mB = m2;
        if (l == 0) {
            if (i < SCAP)     { sAl[i * 8 + 2 * w] = a0A;       sAl[i * 8 + 2 * w + 1] = a0B; }
            if (i + 1 < SCAP) { sAl[(i + 1) * 8 + 2 * w] = a1A; sAl[(i + 1) * 8 + 2 * w + 1] = a1B; }
        }
    }
    if (i < deg) {
        int p0 = e0 + i;
        int s0 = g_csrc[p0], id0 = g_ceid[p0];
        float t0A = 0.f, t0B = 0.f;
#pragma unroll
        for (int j = 0; j < VPT; j++) {
            float k0v = kbuf[s0 * D + cbase + j * 32 + l];
            if (j < VPT / 2) t0A += qreg[j] * k0v; else t0B += qreg[j] * k0v;
        }
        if (l < 22) {
            float a0 = attr[id0 * EDIM + l];
            t0A += a0 * qpA; t0B += a0 * qpB;
        }
#pragma unroll
        for (int o = 16; o; o >>= 1) {
            t0A += __shfl_xor_sync(0xffffffffu, t0A, o);
            t0B += __shfl_xor_sync(0xffffffffu, t0B, o);
        }
        float a0A = t0A * scale, a0B = t0B * scale;
        float m2;
        m2 = fmaxf(mA, a0A); sA = sA * __expf(mA - m2) + __expf(a0A - m2); mA = m2;
        m2 = fmaxf(mB, a0B); sB = sB * __expf(mB - m2) + __expf(a0B - m2); mB = m2;
        if (l == 0 && i < SCAP) { sAl[i * 8 + 2 * w] = a0A; sAl[i * 8 + 2 * w + 1] = a0B; }
    }

    // ---- normalize alphas in smem ----
    __syncwarp();
    float invA = 1.f / (sA + 1e-16f);
    float invB = 1.f / (sB + 1e-16f);
    int degc = (deg < SCAP) ? deg : SCAP;
    for (int ii = l; ii < degc; ii += 32) {
        sAl[ii * 8 + 2 * w]     = __expf(sAl[ii * 8 + 2 * w]     - mA) * invA;
        sAl[ii * 8 + 2 * w + 1] = __expf(sAl[ii * 8 + 2 * w + 1] - mB) * invB;
    }
    __syncwarp();

    // ---- phase B: weighted message + attr aggregation (unrolled by 2) ----
    float acc[VPT];
#pragma unroll
    for (int j = 0; j < VPT; j++) acc[j] = 0.f;
    float aaA = 0.f, aaB = 0.f;

    i = 0;
    for (; i + 2 <= degc; i += 2) {
        int p0 = e0 + i, p1 = e0 + i + 1;
        int s0 = g_csrc[p0], s1 = g_csrc[p1];
        int id0 = g_ceid[p0], id1 = g_ceid[p1];
        float a0A = sAl[i * 8 + 2 * w],       a0B = sAl[i * 8 + 2 * w + 1];
        float a1A = sAl[(i + 1) * 8 + 2 * w], a1B = sAl[(i + 1) * 8 + 2 * w + 1];
#pragma unroll
        for (int j = 0; j < VPT; j++) {
            float v0 = vbuf[s0 * D + cbase + j * 32 + l];
            float v1 = vbuf[s1 * D + cbase + j * 32 + l];
            float c0 = (j < VPT / 2) ? a0A : a0B;
            float c1 = (j < VPT / 2) ? a1A : a1B;
            acc[j] += c0 * v0 + c1 * v1;
        }
        if (l < 22) {
            float a0 = attr[id0 * EDIM + l], a1 = attr[id1 * EDIM + l];
            aaA += a0A * a0 + a1A * a1;
            aaB += a0B * a0 + a1B * a1;
        }
    }
    if (i < degc) {
        int p0 = e0 + i;
        int s0 = g_csrc[p0], id0 = g_ceid[p0];
        float a0A = sAl[i * 8 + 2 * w], a0B = sAl[i * 8 + 2 * w + 1];
#pragma unroll
        for (int j = 0; j < VPT; j++) {
            float v0 = vbuf[s0 * D + cbase + j * 32 + l];
            acc[j] += ((j < VPT / 2) ? a0A : a0B) * v0;
        }
        if (l < 22) {
            float a0 = attr[id0 * EDIM + l];
            aaA += a0A * a0;
            aaB += a0B * a0;
        }
    }
    // rare overflow tail: recompute logits
    for (int ii = SCAP; ii < deg; ii++) {
        int p0 = e0 + ii;
        int s0 = g_csrc[p0], id0 = g_ceid[p0];
        float t0A = 0.f, t0B = 0.f;
#pragma unroll
        for (int j = 0; j < VPT; j++) {
            float k0v = kbuf[s0 * D + cbase + j * 32 + l];
            if (j < VPT / 2) t0A += qreg[j] * k0v; else t0B += qreg[j] * k0v;
        }
        float a0 = (l < 22) ? attr[id0 * EDIM + l] : 0.f;
        if (l < 22) { t0A += a0 * qpA; t0B += a0 * qpB; }
#pragma unroll
        for (int o = 16; o; o >>= 1) {
            t0A += __shfl_xor_sync(0xffffffffu, t0A, o);
            t0B += __shfl_xor_sync(0xffffffffu, t0B, o);
        }
        float a0A = __expf(t0A * scale - mA) * invA;
        float a0B = __expf(t0B * scale - mB) * invB;
#pragma unroll
        for (int j = 0; j < VPT; j++) {
            float v0 = vbuf[s0 * D + cbase + j * 32 + l];
            acc[j] += ((j < VPT / 2) ? a0A : a0B) * v0;
        }
        if (l < 22) { aaA += a0A * a0; aaB += a0B * a0; }
    }

    // attr-message: out_h += (sum_e a_eh * attr_e) @ We_h
    float extra[VPT];
#pragma unroll
    for (int j = 0; j < VPT; j++) extra[j] = 0.f;
    for (int g = 0; g < 22; g++) {
        float gA = __shfl_sync(0xffffffffu, aaA, g);
        float gB = __shfl_sync(0xffffffffu, aaB, g);
#pragma unroll
        for (int j = 0; j < VPT; j++) {
            float wv = we[g * D + cbase + j * 32 + l];
            extra[j] += ((j < VPT / 2) ? gA : gB) * wv;
        }
    }
#pragma unroll
    for (int j = 0; j < VPT; j++) {
        int idx = dst * D + cbase + j * 32 + l;
        float v = outbuf[idx] + acc[j] + extra[j];
        outbuf[idx] = fmaxf(v, 0.f);
    }
}

// ---------------- final: sigmoid(concat(x1,x2) @ w_out + b) -----------------
__global__ void __launch_bounds__(128) k_final(const float* __restrict__ wout,
                                               const float* __restrict__ bout,
                                               float* __restrict__ out) {
    int n = blockIdx.x * 4 + (threadIdx.x >> 5);
    if (n >= NN) return;
    int l = threadIdx.x & 31;
    float s = 0.f;
#pragma unroll
    for (int j = 0; j < 8; j++) {
        int c = l + j * 32;
        s += g_x1[n * D1 + c] * wout[c];
    }
#pragma unroll
    for (int j = 0; j < 16; j++) {
        int c = l + j * 32;
        s += g_x2[n * D2 + c] * wout[256 + c];
    }
#pragma unroll
    for (int o = 16; o; o >>= 1) s += __shfl_xor_sync(0xffffffffu, s, o);
    if (l == 0) out[n] = 1.f / (1.f + expf(-(s + bout[0])));
}

// ---------------- launch ----------------------------------------------------
extern "C" void kernel_launch(void* const* d_in, const int* in_sizes, int n_in,
                              void* d_out, int out_size) {
    const float* x  = (const float*)d_in[0];
    const int*   ei = (const int*)d_in[1];   // int32 OR int64 (device-detected)
    const float* ea = (const float*)d_in[2];
    const float* w1_q = (const float*)d_in[3];  const float* b1_q = (const float*)d_in[4];
    const float* w1_k = (const float*)d_in[5];  const float* b1_k = (const float*)d_in[6];
    const float* w1_v = (const float*)d_in[7];  const float* b1_v = (const float*)d_in[8];
    const float* w1_e = (const float*)d_in[9];
    const float* w1_s = (const float*)d_in[10]; const float* b1_s = (const float*)d_in[11];
    const float* w2_q = (const float*)d_in[12]; const float* b2_q = (const float*)d_in[13];
    const float* w2_k = (const float*)d_in[14]; const float* b2_k = (const float*)d_in[15];
    const float* w2_v = (const float*)d_in[16]; const float* b2_v = (const float*)d_in[17];
    const float* w2_e = (const float*)d_in[18];
    const float* w2_s = (const float*)d_in[19]; const float* b2_s = (const float*)d_in[20];
    const float* w_out = (const float*)d_in[21];
    const float* b_out = (const float*)d_in[22];
    float* out = (float*)d_out;

    static int smem_set = 0;
    if (!smem_set) {
        cudaFuncSetAttribute(k_gemm2_tc,
                             cudaFuncAttributeMaxDynamicSharedMemorySize, G2_SMEM);
        smem_set = 1;
    }

    // dtype probe + CSR build (shared by both layers)
    k_detect<<<1, 32>>>(ei);
    k_zero_counters<<<(NN + 255) / 256, 256>>>();
    k_hist<<<(EE + 255) / 256, 256>>>(ei);
    k_scan1<<<SCB, 1024>>>();
    k_scan2<<<1, 64>>>();
    k_scan3<<<(NN + 255) / 256, 256>>>();
    k_scatter<<<(EE + 255) / 256, 256>>>(ei);

    // layer 1
    k_wcat1<<<(FINN * W1COLS + W1COLS + 255) / 256, 256>>>(w1_q, b1_q, w1_k, b1_k,
                                                           w1_v, b1_v, w1_e, w1_s, b1_s);
    {
        dim3 g((NN + 127) / 128, (W1COLS + 127) / 128);
        k_gemm1<<<g, 256>>>(x);
    }
    k_edge<1><<<NN, 128>>>(ea, w1_e);

    // layer 2 (tensor-core GEMM, double-buffered cp.async)
    k_wcat2<<<(D1 * W2COLS + W2COLS + 255) / 256, 256>>>(w2_q, b2_q, w2_k, b2_k,
                                                         w2_v, b2_v, w2_e, w2_s, b2_s);
    {
        dim3 g((NN + 127) / 128, W2COLS / 128);
        k_gemm2_tc<<<g, 256, G2_SMEM>>>();
    }
    k_edge<2><<<NN, 128>>>(ea, w2_e);

    // output head
    k_final<<<(NN + 3) / 4, 128>>>(w_out, b_out, out);
}

// round 7
// speedup vs baseline: 1.7401x; 1.0414x over previous
#include <cuda_runtime.h>
#include <math.h>

#define NN   50000
#define EE   400000
#define FINN 22
#define EDIM 22
#define HH   8
#define D1   256
#define D2   512
#define QPW  176    /* 8 heads * 22 attr dims */

#define W1COLS 1200    /* 4*256 + 176 */
#define W2COLS 2304    /* 4*512 + 176, padded to 18*128 */
#define W2VALID 2224

#define SCAP 256       /* smem alpha capacity per dst */
#define SCB  49        /* ceil(NN/1024) scan blocks */

// ---------------- scratch (device globals; no allocations allowed) ----------
__device__ float g_q1[NN * D1];
__device__ float g_k1[NN * D1];
__device__ float g_v1[NN * D1];
__device__ float g_x1[NN * D1];
__device__ float g_qp1[NN * QPW];
__device__ float g_q2[NN * D2];
__device__ float g_k2[NN * D2];
__device__ float g_v2[NN * D2];
__device__ float g_x2[NN * D2];
__device__ float g_qp2[NN * QPW];
__device__ int   g_deg[NN];
__device__ int   g_cur[NN];
__device__ int   g_off[NN + 1];
__device__ int   g_csrc[EE];
__device__ int   g_ceid[EE];
__device__ float g_wcat1[FINN * W1COLS];
__device__ float g_bcat1[W1COLS];
__device__ float g_wcat2[D1 * W2COLS];
__device__ float g_bcat2[W2COLS];
__device__ int   g_is64;
__device__ int   g_bsum[SCB];
__device__ int   g_bbase[SCB];

// ---------------- edge_index dtype detection (int32 vs int64) ---------------
__global__ void k_detect(const int* __restrict__ ei) {
    int l = threadIdx.x;
    int nz = 0;
    for (int i = l; i < 1024; i += 32) nz |= (ei[2 * i + 1] != 0);
    unsigned m = __ballot_sync(0xffffffffu, nz);
    if (l == 0) g_is64 = (m == 0);
}

__device__ __forceinline__ int ld_src(const int* __restrict__ ei, int e) {
    return g_is64 ? ei[2 * e] : ei[e];
}
__device__ __forceinline__ int ld_dst(const int* __restrict__ ei, int e) {
    return g_is64 ? ei[2 * (EE + e)] : ei[EE + e];
}

// ---------------- CSR build ----------------
__global__ void k_zero_counters() {
    int i = blockIdx.x * blockDim.x + threadIdx.x;
    if (i < NN) { g_deg[i] = 0; g_cur[i] = 0; }
}

__global__ void k_hist(const int* __restrict__ ei) {
    int e = blockIdx.x * blockDim.x + threadIdx.x;
    if (e < EE) atomicAdd(&g_deg[ld_dst(ei, e)], 1);
}

__global__ void k_scan1() {
    __shared__ int sm[1024];
    int b = blockIdx.x;
    int i = b * 1024 + threadIdx.x;
    int v = (i < NN) ? g_deg[i] : 0;
    sm[threadIdx.x] = v;
    __syncthreads();
    for (int off = 1; off < 1024; off <<= 1) {
        int t = 0;
        if (threadIdx.x >= off) t = sm[threadIdx.x - off];
        __syncthreads();
        if (threadIdx.x >= off) sm[threadIdx.x] += t;
        __syncthreads();
    }
    if (i < NN) g_off[i + 1] = sm[threadIdx.x];
    if (threadIdx.x == 1023) g_bsum[b] = sm[1023];
}
__global__ void k_scan2() {
    if (threadIdx.x == 0) {
        int run = 0;
        for (int b = 0; b < SCB; b++) { g_bbase[b] = run; run += g_bsum[b]; }
        g_off[0] = 0;
    }
}
__global__ void k_scan3() {
    int i = blockIdx.x * blockDim.x + threadIdx.x;
    if (i < NN) g_off[i + 1] += g_bbase[i >> 10];
}

__global__ void k_scatter(const int* __restrict__ ei) {
    int e = blockIdx.x * blockDim.x + threadIdx.x;
    if (e < EE) {
        int src = ld_src(ei, e);
        int dst = ld_dst(ei, e);
        int pos = g_off[dst] + atomicAdd(&g_cur[dst], 1);
        g_csrc[pos] = src;
        g_ceid[pos] = e;
    }
}

// ---------------- weight concat builders (fold qproj = (x@Wq+b)@We_h^T) ----
__global__ void k_wcat1(const float* __restrict__ wq, const float* __restrict__ bq,
                        const float* __restrict__ wk, const float* __restrict__ bk,
                        const float* __restrict__ wv, const float* __restrict__ bv,
                        const float* __restrict__ we,
                        const float* __restrict__ ws, const float* __restrict__ bs) {
    int idx = blockIdx.x * blockDim.x + threadIdx.x;
    int wn = FINN * W1COLS;
    if (idx < wn) {
        int f = idx / W1COLS, c = idx % W1COLS;
        float val;
        if (c < 256)       val = wq[f * 256 + c];
        else if (c < 512)  val = wk[f * 256 + (c - 256)];
        else if (c < 768)  val = wv[f * 256 + (c - 512)];
        else if (c < 1024) val = ws[f * 256 + (c - 768)];
        else {
            int t = c - 1024, h = t / 22, g = t % 22;
            float s = 0.f;
            for (int cc = 0; cc < 32; cc++)
                s += wq[f * 256 + h * 32 + cc] * we[g * 256 + h * 32 + cc];
            val = s;
        }
        g_wcat1[f * W1COLS + c] = val;
    } else if (idx < wn + W1COLS) {
        int c = idx - wn;
        float val;
        if (c < 256)       val = bq[c];
        else if (c < 512)  val = bk[c - 256];
        else if (c < 768)  val = bv[c - 512];
        else if (c < 1024) val = bs[c - 768];
        else {
            int t = c - 1024, h = t / 22, g = t % 22;
            float s = 0.f;
            for (int cc = 0; cc < 32; cc++)
                s += bq[h * 32 + cc] * we[g * 256 + h * 32 + cc];
            val = s;
        }
        g_bcat1[c] = val;
    }
}

__global__ void k_wcat2(const float* __restrict__ wq, const float* __restrict__ bq,
                        const float* __restrict__ wk, const float* __restrict__ bk,
                        const float* __restrict__ wv, const float* __restrict__ bv,
                        const float* __restrict__ we,
                        const float* __restrict__ ws, const float* __restrict__ bs) {
    int idx = blockIdx.x * blockDim.x + threadIdx.x;
    int wn = D1 * W2COLS;
    if (idx < wn) {
        int f = idx / W2COLS, c = idx % W2COLS;
        float val = 0.f;
        if (c < 512)        val = wq[f * 512 + c];
        else if (c < 1024)  val = wk[f * 512 + (c - 512)];
        else if (c < 1536)  val = wv[f * 512 + (c - 1024)];
        else if (c < 2048)  val = ws[f * 512 + (c - 1536)];
        else if (c < W2VALID) {
            int t = c - 2048, h = t / 22, g = t % 22;
            float s = 0.f;
            for (int cc = 0; cc < 64; cc++)
                s += wq[f * 512 + h * 64 + cc] * we[g * 512 + h * 64 + cc];
            val = s;
        }
        g_wcat2[f * W2COLS + c] = val;
    } else if (idx < wn + W2COLS) {
        int c = idx - wn;
        float val = 0.f;
        if (c < 512)        val = bq[c];
        else if (c < 1024)  val = bk[c - 512];
        else if (c < 1536)  val = bv[c - 1024];
        else if (c < 2048)  val = bs[c - 1536];
        else if (c < W2VALID) {
            int t = c - 2048, h = t / 22, g = t % 22;
            float s = 0.f;
            for (int cc = 0; cc < 64; cc++)
                s += bq[h * 64 + cc] * we[g * 512 + h * 64 + cc];
            val = s;
        }
        g_bcat2[c] = val;
    }
}

// ---------------- layer1 node GEMM: x[N,22] @ Wcat1[22,1200] -----------------
__global__ void __launch_bounds__(256) k_gemm1(const float* __restrict__ x) {
    __shared__ float xs[FINN][128];
    __shared__ float ws[FINN][128];
    int m0 = blockIdx.x * 128;
    int c0 = blockIdx.y * 128;
    int t = threadIdx.x;
    for (int i = t; i < 128 * FINN; i += 256) {
        int n = i / FINN, f = i % FINN;
        xs[f][n] = (m0 + n < NN) ? x[(m0 + n) * FINN + f] : 0.f;
    }
    for (int i = t; i < FINN * 128; i += 256) {
        int f = i / 128, cc = i % 128;
        ws[f][cc] = (c0 + cc < W1COLS) ? g_wcat1[f * W1COLS + c0 + cc] : 0.f;
    }
    __syncthreads();
    int tr = t >> 4, tc = t & 15;
    float acc[8][8];
#pragma unroll
    for (int i = 0; i < 8; i++)
#pragma unroll
        for (int j = 0; j < 8; j++) acc[i][j] = 0.f;
#pragma unroll
    for (int f = 0; f < FINN; f++) {
        float a[8], b[8];
        *(float4*)(a)     = *(const float4*)&xs[f][tr * 8];
        *(float4*)(a + 4) = *(const float4*)&xs[f][tr * 8 + 4];
        *(float4*)(b)     = *(const float4*)&ws[f][tc * 8];
        *(float4*)(b + 4) = *(const float4*)&ws[f][tc * 8 + 4];
#pragma unroll
        for (int i = 0; i < 8; i++)
#pragma unroll
            for (int j = 0; j < 8; j++) acc[i][j] += a[i] * b[j];
    }
#pragma unroll
    for (int i = 0; i < 8; i++) {
        int row = m0 + tr * 8 + i;
        if (row >= NN) continue;
#pragma unroll
        for (int j = 0; j < 8; j++) {
            int col = c0 + tc * 8 + j;
            if (col >= W1COLS) continue;
            float v = acc[i][j] + g_bcat1[col];
            if (col < 256)       g_q1[row * D1 + col] = v;
            else if (col < 512)  g_k1[row * D1 + col - 256] = v;
            else if (col < 768)  g_v1[row * D1 + col - 512] = v;
            else if (col < 1024) g_x1[row * D1 + col - 768] = v;
            else                 g_qp1[row * QPW + col - 1024] = v;
        }
    }
}

// ---------------- layer2 GEMM: tf32 mma.sync + cp.async double buffering ----
__device__ __forceinline__ void mma_tf32(float* c, unsigned a0, unsigned a1,
                                         unsigned a2, unsigned a3,
                                         unsigned b0, unsigned b1) {
    asm volatile("mma.sync.aligned.m16n8k8.row.col.f32.tf32.tf32.f32 "
                 "{%0,%1,%2,%3}, {%4,%5,%6,%7}, {%8,%9}, {%0,%1,%2,%3};"
                 : "+f"(c[0]), "+f"(c[1]), "+f"(c[2]), "+f"(c[3])
                 : "r"(a0), "r"(a1), "r"(a2), "r"(a3), "r"(b0), "r"(b1));
}

__device__ __forceinline__ void cp16(void* sptr, const void* gptr) {
    unsigned sa = (unsigned)__cvta_generic_to_shared(sptr);
    asm volatile("cp.async.cg.shared.global [%0], [%1], 16;" :: "r"(sa), "l"(gptr));
}

__device__ __forceinline__ void store_l2(int row, int col, float v) {
    if (row >= NN || col >= W2VALID) return;
    v += g_bcat2[col];
    if (col < 512)       g_q2[row * D2 + col] = v;
    else if (col < 1024) g_k2[row * D2 + col - 512] = v;
    else if (col < 1536) g_v2[row * D2 + col - 1024] = v;
    else if (col < 2048) g_x2[row * D2 + col - 1536] = v;
    else                 g_qp2[row * QPW + col - 2048] = v;
}

#define ASTRIDE 36
#define BSTRIDE 136
#define ASZ (128 * ASTRIDE)
#define BSZ (32 * BSTRIDE)
#define G2_SMEM ((2 * ASZ + 2 * BSZ) * 4)

__global__ void __launch_bounds__(256) k_gemm2_tc() {
    extern __shared__ float sm[];
    float* As[2] = { sm, sm + ASZ };
    float* Bs[2] = { sm + 2 * ASZ, sm + 2 * ASZ + BSZ };

    int m0 = blockIdx.x * 128;
    int c0 = blockIdx.y * 128;
    int t = threadIdx.x;
    int w = t >> 5, l = t & 31;
    int wm = (w >> 2) * 64;
    int wn = (w & 3) * 32;
    int gp = l >> 2, tq = l & 3;

    float acc[4][4][4];
#pragma unroll
    for (int a = 0; a < 4; a++)
#pragma unroll
        for (int b = 0; b < 4; b++)
#pragma unroll
            for (int cc = 0; cc < 4; cc++) acc[a][b][cc] = 0.f;

    auto load_stage = [&](int kc, int s) {
#pragma unroll
        for (int li = 0; li < 4; li++) {
            int idx = t + li * 256;
            int m = idx >> 3, kq = (idx & 7) * 4;
            float* sp = &As[s][m * ASTRIDE + kq];
            if (m0 + m < NN)
                cp16(sp, &g_x1[(m0 + m) * D1 + kc * 32 + kq]);
            else
                *(float4*)sp = make_float4(0.f, 0.f, 0.f, 0.f);
        }
#pragma unroll
        for (int li = 0; li < 4; li++) {
            int idx = t + li * 256;
            int r = idx >> 5, c4 = (idx & 31) * 4;
            cp16(&Bs[s][r * BSTRIDE + c4],
                 &g_wcat2[(kc * 32 + r) * W2COLS + c0 + c4]);
        }
    };

    load_stage(0, 0);
    asm volatile("cp.async.commit_group;");

    for (int kc = 0; kc < 8; kc++) {
        int cur = kc & 1;
        if (kc < 7) {
            load_stage(kc + 1, cur ^ 1);
            asm volatile("cp.async.commit_group;");
            asm volatile("cp.async.wait_group 1;");
        } else {
            asm volatile("cp.async.wait_group 0;");
        }
        __syncthreads();
        const float* A = As[cur];
        const float* B = Bs[cur];
#pragma unroll
        for (int kb = 0; kb < 4; kb++) {
            int k0 = kb * 8;
            unsigned af[4][4], bf[4][2];
#pragma unroll
            for (int mt = 0; mt < 4; mt++) {
                int row = wm + mt * 16 + gp;
                af[mt][0] = __float_as_uint(A[row * ASTRIDE + k0 + tq]);
                af[mt][1] = __float_as_uint(A[(row + 8) * ASTRIDE + k0 + tq]);
                af[mt][2] = __float_as_uint(A[row * ASTRIDE + k0 + tq + 4]);
                af[mt][3] = __float_as_uint(A[(row + 8) * ASTRIDE + k0 + tq + 4]);
            }
#pragma unroll
            for (int nt = 0; nt < 4; nt++) {
                int col = wn + nt * 8 + gp;
                bf[nt][0] = __float_as_uint(B[(k0 + tq) * BSTRIDE + col]);
                bf[nt][1] = __float_as_uint(B[(k0 + tq + 4) * BSTRIDE + col]);
            }
#pragma unroll
            for (int mt = 0; mt < 4; mt++)
#pragma unroll
                for (int nt = 0; nt < 4; nt++)
                    mma_tf32(acc[mt][nt], af[mt][0], af[mt][1], af[mt][2],
                             af[mt][3], bf[nt][0], bf[nt][1]);
        }
        __syncthreads();
    }
#pragma unroll
    for (int mt = 0; mt < 4; mt++) {
        int r0 = m0 + wm + mt * 16 + gp;
#pragma unroll
        for (int nt = 0; nt < 4; nt++) {
            int cb = c0 + wn + nt * 8 + tq * 2;
            store_l2(r0,     cb,     acc[mt][nt][0]);
            store_l2(r0,     cb + 1, acc[mt][nt][1]);
            store_l2(r0 + 8, cb,     acc[mt][nt][2]);
            store_l2(r0 + 8, cb + 1, acc[mt][nt][3]);
        }
    }
}

// ---------------- fused attention (float4 lane-group layout) ----------------
// Each warp owns a contiguous 128-col (512B) chunk of the dst row; lane l owns
// cols 4l..4l+3. Heads map to lane groups (layer1: 8 lanes/head, 4 heads/warp;
// layer2: 16 lanes/head, 2 heads/warp). Layer1 blocks process 2 dst nodes.
template <int LAYER>
__global__ void __launch_bounds__(128) k_edge(const float* __restrict__ attr,
                                              const float* __restrict__ we) {
    constexpr int C   = (LAYER == 1) ? 32 : 64;
    constexpr int D   = 8 * C;
    constexpr int LPH = (LAYER == 1) ? 8 : 16;     // lanes per head
    constexpr int NPB = (LAYER == 1) ? 2 : 1;      // nodes per block
    constexpr int WPN = 4 / NPB;                   // warps per node
    const float* kbuf  = (LAYER == 1) ? g_k1 : g_k2;
    const float* qbuf  = (LAYER == 1) ? g_q1 : g_q2;
    const float* qpbuf = (LAYER == 1) ? g_qp1 : g_qp2;
    const float* vbuf  = (LAYER == 1) ? g_v1 : g_v2;
    float* outbuf      = (LAYER == 1) ? g_x1 : g_x2;  // pre-seeded with skip
    const float scale = (LAYER == 1) ? 0.17677669529663687f : 0.125f;

    int w = threadIdx.x >> 5, l = threadIdx.x & 31;
    int node = w / WPN;                 // node slot within block
    int wl = w % WPN;                   // warp index within node
    int dst = blockIdx.x * NPB + node;
    int cbase = wl * 128;               // column base (floats)
    int h = (LAYER == 1) ? (wl * 4 + (l >> 3)) : (wl * 2 + (l >> 4));
    int j = l & (LPH - 1);              // lane within head group
    int gb = l & ~(LPH - 1);            // group base lane

    int e0 = g_off[dst], deg = g_off[dst + 1] - e0;

    // q fragment + per-head qp (attr-projection of q)
    float4 q4 = *(const float4*)&qbuf[dst * D + cbase + 4 * l];
    const float* qp = &qpbuf[dst * QPW + h * 22];
    float qp0, qp1, qp2 = 0.f;
    if (LAYER == 1) {
        qp0 = qp[j]; qp1 = qp[8 + j]; qp2 = (j < 6) ? qp[16 + j] : 0.f;
    } else {
        qp0 = qp[j]; qp1 = (j < 6) ? qp[16 + j] : 0.f;
    }

    __shared__ float sAl[NPB * SCAP * 8];
    float* sA = &sAl[node * SCAP * 8];

    float m = -1e30f, s = 0.f;

    // ---- phase A: logits + online softmax (per-head lane groups) ----
    auto logit = [&](int pos) -> float {
        int srcn = g_csrc[pos];
        int eid = g_ceid[pos];
        float4 k4 = __ldg((const float4*)&kbuf[srcn * D + cbase + 4 * l]);
        float t = q4.x * k4.x + q4.y * k4.y + q4.z * k4.z + q4.w * k4.w;
        const float* ar = &attr[eid * EDIM];
        if (LAYER == 1) {
            float a0 = __ldg(&ar[j]), a1 = __ldg(&ar[8 + j]);
            float a2 = (j < 6) ? __ldg(&ar[16 + j]) : 0.f;
            t += a0 * qp0 + a1 * qp1 + a2 * qp2;
        } else {
            float a0 = __ldg(&ar[j]);
            float a1 = (j < 6) ? __ldg(&ar[16 + j]) : 0.f;
            t += a0 * qp0 + a1 * qp1;
        }
#pragma unroll
        for (int o = LPH / 2; o; o >>= 1)
            t += __shfl_xor_sync(0xffffffffu, t, o);
        return t * scale;
    };

    int i = 0;
    for (; i + 2 <= deg; i += 2) {
        float lg0 = logit(e0 + i);
        float lg1 = logit(e0 + i + 1);
        float m2;
        m2 = fmaxf(m, lg0); s = s * __expf(m - m2) + __expf(lg0 - m2); m = m2;
        m2 = fmaxf(m, lg1); s = s * __expf(m - m2) + __expf(lg1 - m2); m = m2;
        if (j == 0) {
            if (i < SCAP)     sA[i * 8 + h] = lg0;
            if (i + 1 < SCAP) sA[(i + 1) * 8 + h] = lg1;
        }
    }
    if (i < deg) {
        float lg0 = logit(e0 + i);
        float m2 = fmaxf(m, lg0);
        s = s * __expf(m - m2) + __expf(lg0 - m2); m = m2;
        if (j == 0 && i < SCAP) sA[i * 8 + h] = lg0;
    }

    // ---- normalize alphas in smem (each group handles its own head) ----
    __syncwarp();
    float inv = 1.f / (s + 1e-16f);
    int degc = (deg < SCAP) ? deg : SCAP;
    for (int ii = j; ii < degc; ii += LPH)
        sA[ii * 8 + h] = __expf(sA[ii * 8 + h] - m) * inv;
    __syncwarp();

    // ---- phase B: weighted message + attr aggregation ----
    float4 acc = make_float4(0.f, 0.f, 0.f, 0.f);
    float aa0 = 0.f, aa1 = 0.f, aa2 = 0.f;

    i = 0;
    for (; i + 2 <= degc; i += 2) {
        int p0 = e0 + i, p1 = e0 + i + 1;
        int s0 = g_csrc[p0], s1 = g_csrc[p1];
        int id0 = g_ceid[p0], id1 = g_ceid[p1];
        float al0 = sA[i * 8 + h], al1 = sA[(i + 1) * 8 + h];
        float4 v0 = __ldg((const float4*)&vbuf[s0 * D + cbase + 4 * l]);
        float4 v1 = __ldg((const float4*)&vbuf[s1 * D + cbase + 4 * l]);
        acc.x += al0 * v0.x + al1 * v1.x;
        acc.y += al0 * v0.y + al1 * v1.y;
        acc.z += al0 * v0.z + al1 * v1.z;
        acc.w += al0 * v0.w + al1 * v1.w;
        const float* a0r = &attr[id0 * EDIM];
        const float* a1r = &attr[id1 * EDIM];
        if (LAYER == 1) {
            aa0 += al0 * __ldg(&a0r[j])     + al1 * __ldg(&a1r[j]);
            aa1 += al0 * __ldg(&a0r[8 + j]) + al1 * __ldg(&a1r[8 + j]);
            if (j < 6) aa2 += al0 * __ldg(&a0r[16 + j]) + al1 * __ldg(&a1r[16 + j]);
        } else {
            aa0 += al0 * __ldg(&a0r[j]) + al1 * __ldg(&a1r[j]);
            if (j < 6) aa1 += al0 * __ldg(&a0r[16 + j]) + al1 * __ldg(&a1r[16 + j]);
        }
    }
    if (i < degc) {
        int p0 = e0 + i;
        int s0 = g_csrc[p0], id0 = g_ceid[p0];
        float al0 = sA[i * 8 + h];
        float4 v0 = __ldg((const float4*)&vbuf[s0 * D + cbase + 4 * l]);
        acc.x += al0 * v0.x; acc.y += al0 * v0.y;
        acc.z += al0 * v0.z; acc.w += al0 * v0.w;
        const float* a0r = &attr[id0 * EDIM];
        if (LAYER == 1) {
            aa0 += al0 * __ldg(&a0r[j]);
            aa1 += al0 * __ldg(&a0r[8 + j]);
            if (j < 6) aa2 += al0 * __ldg(&a0r[16 + j]);
        } else {
            aa0 += al0 * __ldg(&a0r[j]);
            if (j < 6) aa1 += al0 * __ldg(&a0r[16 + j]);
        }
    }
    // rare overflow tail (deg > SCAP): recompute logits
    for (int ii = SCAP; ii < deg; ii++) {
        int p0 = e0 + ii;
        int s0 = g_csrc[p0], id0 = g_ceid[p0];
        float al0 = __expf(logit(p0) - m) * inv;
        float4 v0 = __ldg((const float4*)&vbuf[s0 * D + cbase + 4 * l]);
        acc.x += al0 * v0.x; acc.y += al0 * v0.y;
        acc.z += al0 * v0.z; acc.w += al0 * v0.w;
        const float* a0r = &attr[id0 * EDIM];
        if (LAYER == 1) {
            aa0 += al0 * __ldg(&a0r[j]);
            aa1 += al0 * __ldg(&a0r[8 + j]);
            if (j < 6) aa2 += al0 * __ldg(&a0r[16 + j]);
        } else {
            aa0 += al0 * __ldg(&a0r[j]);
            if (j < 6) aa1 += al0 * __ldg(&a0r[16 + j]);
        }
    }

    // ---- attr-message: out_h += (sum_e a_eh * attr_e) @ We_h ----
    float4 ex = make_float4(0.f, 0.f, 0.f, 0.f);
#pragma unroll
    for (int g = 0; g < 22; g++) {
        float aag;
        if (g < LPH)            aag = __shfl_sync(0xffffffffu, aa0, gb + g);
        else if (g < 2 * LPH)   aag = __shfl_sync(0xffffffffu, aa1, gb + g - LPH);
        else                    aag = __shfl_sync(0xffffffffu, aa2, gb + g - 2 * LPH);
        float4 w4 = __ldg((const float4*)&we[g * D + cbase + 4 * l]);
        ex.x += aag * w4.x; ex.y += aag * w4.y;
        ex.z += aag * w4.z; ex.w += aag * w4.w;
    }

    int idx = dst * D + cbase + 4 * l;
    float4 o = *(float4*)&outbuf[idx];
    o.x = fmaxf(o.x + acc.x + ex.x, 0.f);
    o.y = fmaxf(o.y + acc.y + ex.y, 0.f);
    o.z = fmaxf(o.z + acc.z + ex.z, 0.f);
    o.w = fmaxf(o.w + acc.w + ex.w, 0.f);
    *(float4*)&outbuf[idx] = o;
}

// ---------------- final: sigmoid(concat(x1,x2) @ w_out + b) -----------------
__global__ void __launch_bounds__(128) k_final(const float* __restrict__ wout,
                                               const float* __restrict__ bout,
                                               float* __restrict__ out) {
    int n = blockIdx.x * 4 + (threadIdx.x >> 5);
    if (n >= NN) return;
    int l = threadIdx.x & 31;
    float s = 0.f;
#pragma unroll
    for (int j = 0; j < 2; j++) {
        int c = (l + j * 32) * 4;
        float4 xv = *(const float4*)&g_x1[n * D1 + c];
        float4 wv = __ldg((const float4*)&wout[c]);
        s += xv.x * wv.x + xv.y * wv.y + xv.z * wv.z + xv.w * wv.w;
    }
#pragma unroll
    for (int j = 0; j < 4; j++) {
        int c = (l + j * 32) * 4;
        float4 xv = *(const float4*)&g_x2[n * D2 + c];
        float4 wv = __ldg((const float4*)&wout[256 + c]);
        s += xv.x * wv.x + xv.y * wv.y + xv.z * wv.z + xv.w * wv.w;
    }
#pragma unroll
    for (int o = 16; o; o >>= 1) s += __shfl_xor_sync(0xffffffffu, s, o);
    if (l == 0) out[n] = 1.f / (1.f + expf(-(s + bout[0])));
}

// ---------------- launch ----------------------------------------------------
extern "C" void kernel_launch(void* const* d_in, const int* in_sizes, int n_in,
                              void* d_out, int out_size) {
    const float* x  = (const float*)d_in[0];
    const int*   ei = (const int*)d_in[1];   // int32 OR int64 (device-detected)
    const float* ea = (const float*)d_in[2];
    const float* w1_q = (const float*)d_in[3];  const float* b1_q = (const float*)d_in[4];
    const float* w1_k = (const float*)d_in[5];  const float* b1_k = (const float*)d_in[6];
    const float* w1_v = (const float*)d_in[7];  const float* b1_v = (const float*)d_in[8];
    const float* w1_e = (const float*)d_in[9];
    const float* w1_s = (const float*)d_in[10]; const float* b1_s = (const float*)d_in[11];
    const float* w2_q = (const float*)d_in[12]; const float* b2_q = (const float*)d_in[13];
    const float* w2_k = (const float*)d_in[14]; const float* b2_k = (const float*)d_in[15];
    const float* w2_v = (const float*)d_in[16]; const float* b2_v = (const float*)d_in[17];
    const float* w2_e = (const float*)d_in[18];
    const float* w2_s = (const float*)d_in[19]; const float* b2_s = (const float*)d_in[20];
    const float* w_out = (const float*)d_in[21];
    const float* b_out = (const float*)d_in[22];
    float* out = (float*)d_out;

    static int smem_set = 0;
    if (!smem_set) {
        cudaFuncSetAttribute(k_gemm2_tc,
                             cudaFuncAttributeMaxDynamicSharedMemorySize, G2_SMEM);
        smem_set = 1;
    }

    // dtype probe + CSR build (shared by both layers)
    k_detect<<<1, 32>>>(ei);
    k_zero_counters<<<(NN + 255) / 256, 256>>>();
    k_hist<<<(EE + 255) / 256, 256>>>(ei);
    k_scan1<<<SCB, 1024>>>();
    k_scan2<<<1, 64>>>();
    k_scan3<<<(NN + 255) / 256, 256>>>();
    k_scatter<<<(EE + 255) / 256, 256>>>(ei);

    // layer 1
    k_wcat1<<<(FINN * W1COLS + W1COLS + 255) / 256, 256>>>(w1_q, b1_q, w1_k, b1_k,
                                                           w1_v, b1_v, w1_e, w1_s, b1_s);
    {
        dim3 g((NN + 127) / 128, (W1COLS + 127) / 128);
        k_gemm1<<<g, 256>>>(x);
    }
    k_edge<1><<<NN / 2, 128>>>(ea, w1_e);

    // layer 2 (tensor-core GEMM, double-buffered cp.async)
    k_wcat2<<<(D1 * W2COLS + W2COLS + 255) / 256, 256>>>(w2_q, b2_q, w2_k, b2_k,
                                                         w2_v, b2_v, w2_e, w2_s, b2_s);
    {
        dim3 g((NN + 127) / 128, W2COLS / 128);
        k_gemm2_tc<<<g, 256, G2_SMEM>>>();
    }
    k_edge<2><<<NN, 128>>>(ea, w2_e);

    // output head
    k_final<<<(NN + 3) / 4, 128>>>(w_out, b_out, out);
}

// round 8
// speedup vs baseline: 2.0739x; 1.1919x over previous
#include <cuda_runtime.h>
#include <math.h>

#define NN   50000
#define EE   400000
#define FINN 22
#define EDIM 22
#define D1   256
#define D2   512
#define QPW  176

#define W1COLS 1200    /* q(256)|k(256)|v(256)|skip(256)|qp(176) */
#define W2COLS 2304    /* q(512)|k(512)|v(512)|skip(512)|qp(176)|pad(80) */
#define W2VALID 2224

#define SCAP 256
#define SCB  49

// ---------------- scratch ----------------------------------------------------
__device__ float g_y1[NN * W1COLS];   // layer1 projections, row-major
__device__ float g_x1[NN * D1];       // layer1 output (dense, gemm2 A)
__device__ float g_y2[NN * W2COLS];   // layer2 projections, row-major
__device__ int   g_deg[NN];
__device__ int   g_cur[NN];
__device__ int   g_off[NN + 1];
__device__ int   g_csrc[EE];
__device__ int   g_ceid[EE];
__device__ float g_wcat1[FINN * W1COLS];
__device__ float g_bcat1[W1COLS];
__device__ float g_wcat2[D1 * W2COLS];
__device__ float g_bcat2[W2COLS];
__device__ int   g_is64;
__device__ int   g_bsum[SCB];
__device__ int   g_bbase[SCB];

// ---------------- edge_index dtype detection --------------------------------
__global__ void k_detect(const int* __restrict__ ei) {
    int l = threadIdx.x;
    int nz = 0;
    for (int i = l; i < 1024; i += 32) nz |= (ei[2 * i + 1] != 0);
    unsigned m = __ballot_sync(0xffffffffu, nz);
    if (l == 0) g_is64 = (m == 0);
}
__device__ __forceinline__ int ld_src(const int* __restrict__ ei, int e) {
    return g_is64 ? ei[2 * e] : ei[e];
}
__device__ __forceinline__ int ld_dst(const int* __restrict__ ei, int e) {
    return g_is64 ? ei[2 * (EE + e)] : ei[EE + e];
}

// ---------------- CSR build ----------------
__global__ void k_zero_counters() {
    int i = blockIdx.x * blockDim.x + threadIdx.x;
    if (i < NN) { g_deg[i] = 0; g_cur[i] = 0; }
}
__global__ void k_hist(const int* __restrict__ ei) {
    int e = blockIdx.x * blockDim.x + threadIdx.x;
    if (e < EE) atomicAdd(&g_deg[ld_dst(ei, e)], 1);
}
__global__ void k_scan1() {
    __shared__ int sm[1024];
    int b = blockIdx.x;
    int i = b * 1024 + threadIdx.x;
    int v = (i < NN) ? g_deg[i] : 0;
    sm[threadIdx.x] = v;
    __syncthreads();
    for (int off = 1; off < 1024; off <<= 1) {
        int t = 0;
        if (threadIdx.x >= off) t = sm[threadIdx.x - off];
        __syncthreads();
        if (threadIdx.x >= off) sm[threadIdx.x] += t;
        __syncthreads();
    }
    if (i < NN) g_off[i + 1] = sm[threadIdx.x];
    if (threadIdx.x == 1023) g_bsum[b] = sm[1023];
}
__global__ void k_scan2() {
    if (threadIdx.x == 0) {
        int run = 0;
        for (int b = 0; b < SCB; b++) { g_bbase[b] = run; run += g_bsum[b]; }
        g_off[0] = 0;
    }
}
__global__ void k_scan3() {
    int i = blockIdx.x * blockDim.x + threadIdx.x;
    if (i < NN) g_off[i + 1] += g_bbase[i >> 10];
}
__global__ void k_scatter(const int* __restrict__ ei) {
    int e = blockIdx.x * blockDim.x + threadIdx.x;
    if (e < EE) {
        int src = ld_src(ei, e);
        int dst = ld_dst(ei, e);
        int pos = g_off[dst] + atomicAdd(&g_cur[dst], 1);
        g_csrc[pos] = src;
        g_ceid[pos] = e;
    }
}

// ---------------- weight concat builders -------------------------------------
__global__ void k_wcat1(const float* __restrict__ wq, const float* __restrict__ bq,
                        const float* __restrict__ wk, const float* __restrict__ bk,
                        const float* __restrict__ wv, const float* __restrict__ bv,
                        const float* __restrict__ we,
                        const float* __restrict__ ws, const float* __restrict__ bs) {
    int idx = blockIdx.x * blockDim.x + threadIdx.x;
    int wn = FINN * W1COLS;
    if (idx < wn) {
        int f = idx / W1COLS, c = idx % W1COLS;
        float val;
        if (c < 256)       val = wq[f * 256 + c];
        else if (c < 512)  val = wk[f * 256 + (c - 256)];
        else if (c < 768)  val = wv[f * 256 + (c - 512)];
        else if (c < 1024) val = ws[f * 256 + (c - 768)];
        else {
            int t = c - 1024, h = t / 22, g = t % 22;
            float s = 0.f;
            for (int cc = 0; cc < 32; cc++)
                s += wq[f * 256 + h * 32 + cc] * we[g * 256 + h * 32 + cc];
            val = s;
        }
        g_wcat1[f * W1COLS + c] = val;
    } else if (idx < wn + W1COLS) {
        int c = idx - wn;
        float val;
        if (c < 256)       val = bq[c];
        else if (c < 512)  val = bk[c - 256];
        else if (c < 768)  val = bv[c - 512];
        else if (c < 1024) val = bs[c - 768];
        else {
            int t = c - 1024, h = t / 22, g = t % 22;
            float s = 0.f;
            for (int cc = 0; cc < 32; cc++)
                s += bq[h * 32 + cc] * we[g * 256 + h * 32 + cc];
            val = s;
        }
        g_bcat1[c] = val;
    }
}

__global__ void k_wcat2(const float* __restrict__ wq, const float* __restrict__ bq,
                        const float* __restrict__ wk, const float* __restrict__ bk,
                        const float* __restrict__ wv, const float* __restrict__ bv,
                        const float* __restrict__ we,
                        const float* __restrict__ ws, const float* __restrict__ bs) {
    int idx = blockIdx.x * blockDim.x + threadIdx.x;
    int wn = D1 * W2COLS;
    if (idx < wn) {
        int f = idx / W2COLS, c = idx % W2COLS;
        float val = 0.f;
        if (c < 512)        val = wq[f * 512 + c];
        else if (c < 1024)  val = wk[f * 512 + (c - 512)];
        else if (c < 1536)  val = wv[f * 512 + (c - 1024)];
        else if (c < 2048)  val = ws[f * 512 + (c - 1536)];
        else if (c < W2VALID) {
            int t = c - 2048, h = t / 22, g = t % 22;
            float s = 0.f;
            for (int cc = 0; cc < 64; cc++)
                s += wq[f * 512 + h * 64 + cc] * we[g * 512 + h * 64 + cc];
            val = s;
        }
        g_wcat2[f * W2COLS + c] = val;
    } else if (idx < wn + W2COLS) {
        int c = idx - wn;
        float val = 0.f;
        if (c < 512)        val = bq[c];
        else if (c < 1024)  val = bk[c - 512];
        else if (c < 1536)  val = bv[c - 1024];
        else if (c < 2048)  val = bs[c - 1536];
        else if (c < W2VALID) {
            int t = c - 2048, h = t / 22, g = t % 22;
            float s = 0.f;
            for (int cc = 0; cc < 64; cc++)
                s += bq[h * 64 + cc] * we[g * 512 + h * 64 + cc];
            val = s;
        }
        g_bcat2[c] = val;
    }
}

// ---------------- layer1 node GEMM -> g_y1 (contiguous stores) ---------------
__global__ void __launch_bounds__(256) k_gemm1(const float* __restrict__ x) {
    __shared__ float xs[FINN][128];
    __shared__ float ws[FINN][128];
    int m0 = blockIdx.x * 128;
    int c0 = blockIdx.y * 128;
    int t = threadIdx.x;
    for (int i = t; i < 128 * FINN; i += 256) {
        int n = i / FINN, f = i % FINN;
        xs[f][n] = (m0 + n < NN) ? x[(m0 + n) * FINN + f] : 0.f;
    }
    for (int i = t; i < FINN * 128; i += 256) {
        int f = i / 128, cc = i % 128;
        ws[f][cc] = (c0 + cc < W1COLS) ? g_wcat1[f * W1COLS + c0 + cc] : 0.f;
    }
    __syncthreads();
    int tr = t >> 4, tc = t & 15;
    float acc[8][8];
#pragma unroll
    for (int i = 0; i < 8; i++)
#pragma unroll
        for (int j = 0; j < 8; j++) acc[i][j] = 0.f;
#pragma unroll
    for (int f = 0; f < FINN; f++) {
        float a[8], b[8];
        *(float4*)(a)     = *(const float4*)&xs[f][tr * 8];
        *(float4*)(a + 4) = *(const float4*)&xs[f][tr * 8 + 4];
        *(float4*)(b)     = *(const float4*)&ws[f][tc * 8];
        *(float4*)(b + 4) = *(const float4*)&ws[f][tc * 8 + 4];
#pragma unroll
        for (int i = 0; i < 8; i++)
#pragma unroll
            for (int j = 0; j < 8; j++) acc[i][j] += a[i] * b[j];
    }
    int cb = c0 + tc * 8;
    float bb[8];
    if (cb + 7 < W1COLS) {
        *(float4*)(bb)     = *(const float4*)&g_bcat1[cb];
        *(float4*)(bb + 4) = *(const float4*)&g_bcat1[cb + 4];
#pragma unroll
        for (int i = 0; i < 8; i++) {
            int row = m0 + tr * 8 + i;
            if (row >= NN) continue;
            float4 o0 = make_float4(acc[i][0] + bb[0], acc[i][1] + bb[1],
                                    acc[i][2] + bb[2], acc[i][3] + bb[3]);
            float4 o1 = make_float4(acc[i][4] + bb[4], acc[i][5] + bb[5],
                                    acc[i][6] + bb[6], acc[i][7] + bb[7]);
            *(float4*)&g_y1[row * W1COLS + cb]     = o0;
            *(float4*)&g_y1[row * W1COLS + cb + 4] = o1;
        }
    }
}

// ---------------- layer2 GEMM: tf32 mma + cp.async -> g_y2 -------------------
__device__ __forceinline__ void mma_tf32(float* c, unsigned a0, unsigned a1,
                                         unsigned a2, unsigned a3,
                                         unsigned b0, unsigned b1) {
    asm volatile("mma.sync.aligned.m16n8k8.row.col.f32.tf32.tf32.f32 "
                 "{%0,%1,%2,%3}, {%4,%5,%6,%7}, {%8,%9}, {%0,%1,%2,%3};"
                 : "+f"(c[0]), "+f"(c[1]), "+f"(c[2]), "+f"(c[3])
                 : "r"(a0), "r"(a1), "r"(a2), "r"(a3), "r"(b0), "r"(b1));
}
__device__ __forceinline__ void cp16(void* sptr, const void* gptr) {
    unsigned sa = (unsigned)__cvta_generic_to_shared(sptr);
    asm volatile("cp.async.cg.shared.global [%0], [%1], 16;" :: "r"(sa), "l"(gptr));
}

#define ASTRIDE 36
#define BSTRIDE 136
#define ASZ (128 * ASTRIDE)
#define BSZ (32 * BSTRIDE)
#define G2_SMEM ((2 * ASZ + 2 * BSZ) * 4)

__global__ void __launch_bounds__(256) k_gemm2_tc() {
    extern __shared__ float sm[];
    float* As[2] = { sm, sm + ASZ };
    float* Bs[2] = { sm + 2 * ASZ, sm + 2 * ASZ + BSZ };

    int m0 = blockIdx.x * 128;
    int c0 = blockIdx.y * 128;
    int t = threadIdx.x;
    int w = t >> 5, l = t & 31;
    int wm = (w >> 2) * 64;
    int wn = (w & 3) * 32;
    int gp = l >> 2, tq = l & 3;

    float acc[4][4][4];
#pragma unroll
    for (int a = 0; a < 4; a++)
#pragma unroll
        for (int b = 0; b < 4; b++)
#pragma unroll
            for (int cc = 0; cc < 4; cc++) acc[a][b][cc] = 0.f;

    auto load_stage = [&](int kc, int s) {
#pragma unroll
        for (int li = 0; li < 4; li++) {
            int idx = t + li * 256;
            int m = idx >> 3, kq = (idx & 7) * 4;
            float* sp = &As[s][m * ASTRIDE + kq];
            if (m0 + m < NN)
                cp16(sp, &g_x1[(m0 + m) * D1 + kc * 32 + kq]);
            else
                *(float4*)sp = make_float4(0.f, 0.f, 0.f, 0.f);
        }
#pragma unroll
        for (int li = 0; li < 4; li++) {
            int idx = t + li * 256;
            int r = idx >> 5, c4 = (idx & 31) * 4;
            cp16(&Bs[s][r * BSTRIDE + c4],
                 &g_wcat2[(kc * 32 + r) * W2COLS + c0 + c4]);
        }
    };

    load_stage(0, 0);
    asm volatile("cp.async.commit_group;");

    for (int kc = 0; kc < 8; kc++) {
        int cur = kc & 1;
        if (kc < 7) {
            load_stage(kc + 1, cur ^ 1);
            asm volatile("cp.async.commit_group;");
            asm volatile("cp.async.wait_group 1;");
        } else {
            asm volatile("cp.async.wait_group 0;");
        }
        __syncthreads();
        const float* A = As[cur];
        const float* B = Bs[cur];
#pragma unroll
        for (int kb = 0; kb < 4; kb++) {
            int k0 = kb * 8;
            unsigned af[4][4], bf[4][2];
#pragma unroll
            for (int mt = 0; mt < 4; mt++) {
                int row = wm + mt * 16 + gp;
                af[mt][0] = __float_as_uint(A[row * ASTRIDE + k0 + tq]);
                af[mt][1] = __float_as_uint(A[(row + 8) * ASTRIDE + k0 + tq]);
                af[mt][2] = __float_as_uint(A[row * ASTRIDE + k0 + tq + 4]);
                af[mt][3] = __float_as_uint(A[(row + 8) * ASTRIDE + k0 + tq + 4]);
            }
#pragma unroll
            for (int nt = 0; nt < 4; nt++) {
                int col = wn + nt * 8 + gp;
                bf[nt][0] = __float_as_uint(B[(k0 + tq) * BSTRIDE + col]);
                bf[nt][1] = __float_as_uint(B[(k0 + tq + 4) * BSTRIDE + col]);
            }
#pragma unroll
            for (int mt = 0; mt < 4; mt++)
#pragma unroll
                for (int nt = 0; nt < 4; nt++)
                    mma_tf32(acc[mt][nt], af[mt][0], af[mt][1], af[mt][2],
                             af[mt][3], bf[nt][0], bf[nt][1]);
        }
        __syncthreads();
    }
    // epilogue: contiguous float2 stores into unified g_y2
#pragma unroll
    for (int mt = 0; mt < 4; mt++) {
        int r0 = m0 + wm + mt * 16 + gp;
#pragma unroll
        for (int nt = 0; nt < 4; nt++) {
            int cb = c0 + wn + nt * 8 + tq * 2;
            float b0 = g_bcat2[cb], b1 = g_bcat2[cb + 1];
            if (r0 < NN)
                *(float2*)&g_y2[r0 * W2COLS + cb] =
                    make_float2(acc[mt][nt][0] + b0, acc[mt][nt][1] + b1);
            if (r0 + 8 < NN)
                *(float2*)&g_y2[(r0 + 8) * W2COLS + cb] =
                    make_float2(acc[mt][nt][2] + b0, acc[mt][nt][3] + b1);
        }
    }
}

// ---------------- fused attention (float4 lane groups, unified buffers) ------
// LAYER==2 also fuses the output head: out[dst] = sigmoid([x1|x2] @ w_out + b).
template <int LAYER>
__global__ void __launch_bounds__(128) k_edge(const float* __restrict__ attr,
                                              const float* __restrict__ we,
                                              const float* __restrict__ wout,
                                              const float* __restrict__ bout,
                                              float* __restrict__ out) {
    constexpr int C   = (LAYER == 1) ? 32 : 64;
    constexpr int D   = 8 * C;
    constexpr int RS  = (LAYER == 1) ? W1COLS : W2COLS;  // row stride in ybuf
    constexpr int OK  = D;           // k column offset
    constexpr int OV  = 2 * D;       // v column offset
    constexpr int OS  = 3 * D;       // skip column offset
    constexpr int OQP = 4 * D;       // qp column offset
    constexpr int LPH = (LAYER == 1) ? 8 : 16;
    constexpr int NPB = (LAYER == 1) ? 2 : 1;
    constexpr int WPN = 4 / NPB;
    const float* ybuf = (LAYER == 1) ? g_y1 : g_y2;
    const float scale = (LAYER == 1) ? 0.17677669529663687f : 0.125f;

    int w = threadIdx.x >> 5, l = threadIdx.x & 31;
    int node = w / WPN;
    int wl = w % WPN;
    int dst = blockIdx.x * NPB + node;
    int cbase = wl * 128;
    int h = (LAYER == 1) ? (wl * 4 + (l >> 3)) : (wl * 2 + (l >> 4));
    int j = l & (LPH - 1);
    int gb = l & ~(LPH - 1);

    int e0 = g_off[dst], deg = g_off[dst + 1] - e0;
    const float* drow = &ybuf[(size_t)dst * RS];

    float4 q4 = *(const float4*)&drow[cbase + 4 * l];
    const float* qp = &drow[OQP + h * 22];
    float qp0, qp1, qp2 = 0.f;
    if (LAYER == 1) {
        qp0 = qp[j]; qp1 = qp[8 + j]; qp2 = (j < 6) ? qp[16 + j] : 0.f;
    } else {
        qp0 = qp[j]; qp1 = (j < 6) ? qp[16 + j] : 0.f;
    }

    __shared__ float sAl[NPB * SCAP * 8];
    float* sA = &sAl[node * SCAP * 8];

    float m = -1e30f, s = 0.f;

    auto logit = [&](int pos) -> float {
        int srcn = g_csrc[pos];
        int eid = g_ceid[pos];
        float4 k4 = __ldg((const float4*)&ybuf[(size_t)srcn * RS + OK + cbase + 4 * l]);
        float t = q4.x * k4.x + q4.y * k4.y + q4.z * k4.z + q4.w * k4.w;
        const float* ar = &attr[eid * EDIM];
        if (LAYER == 1) {
            float a0 = __ldg(&ar[j]), a1 = __ldg(&ar[8 + j]);
            float a2 = (j < 6) ? __ldg(&ar[16 + j]) : 0.f;
            t += a0 * qp0 + a1 * qp1 + a2 * qp2;
        } else {
            float a0 = __ldg(&ar[j]);
            float a1 = (j < 6) ? __ldg(&ar[16 + j]) : 0.f;
            t += a0 * qp0 + a1 * qp1;
        }
#pragma unroll
        for (int o = LPH / 2; o; o >>= 1)
            t += __shfl_xor_sync(0xffffffffu, t, o);
        return t * scale;
    };

    int i = 0;
    for (; i + 2 <= deg; i += 2) {
        float lg0 = logit(e0 + i);
        float lg1 = logit(e0 + i + 1);
        float m2;
        m2 = fmaxf(m, lg0); s = s * __expf(m - m2) + __expf(lg0 - m2); m = m2;
        m2 = fmaxf(m, lg1); s = s * __expf(m - m2) + __expf(lg1 - m2); m = m2;
        if (j == 0) {
            if (i < SCAP)     sA[i * 8 + h] = lg0;
            if (i + 1 < SCAP) sA[(i + 1) * 8 + h] = lg1;
        }
    }
    if (i < deg) {
        float lg0 = logit(e0 + i);
        float m2 = fmaxf(m, lg0);
        s = s * __expf(m - m2) + __expf(lg0 - m2); m = m2;
        if (j == 0 && i < SCAP) sA[i * 8 + h] = lg0;
    }

    __syncwarp();
    float inv = 1.f / (s + 1e-16f);
    int degc = (deg < SCAP) ? deg : SCAP;
    for (int ii = j; ii < degc; ii += LPH)
        sA[ii * 8 + h] = __expf(sA[ii * 8 + h] - m) * inv;
    __syncwarp();

    float4 acc = make_float4(0.f, 0.f, 0.f, 0.f);
    float aa0 = 0.f, aa1 = 0.f, aa2 = 0.f;

    i = 0;
    for (; i + 2 <= degc; i += 2) {
        int p0 = e0 + i, p1 = e0 + i + 1;
        int s0 = g_csrc[p0], s1 = g_csrc[p1];
        int id0 = g_ceid[p0], id1 = g_ceid[p1];
        float al0 = sA[i * 8 + h], al1 = sA[(i + 1) * 8 + h];
        float4 v0 = __ldg((const float4*)&ybuf[(size_t)s0 * RS + OV + cbase + 4 * l]);
        float4 v1 = __ldg((const float4*)&ybuf[(size_t)s1 * RS + OV + cbase + 4 * l]);
        acc.x += al0 * v0.x + al1 * v1.x;
        acc.y += al0 * v0.y + al1 * v1.y;
        acc.z += al0 * v0.z + al1 * v1.z;
        acc.w += al0 * v0.w + al1 * v1.w;
        const float* a0r = &attr[id0 * EDIM];
        const float* a1r = &attr[id1 * EDIM];
        if (LAYER == 1) {
            aa0 += al0 * __ldg(&a0r[j])     + al1 * __ldg(&a1r[j]);
            aa1 += al0 * __ldg(&a0r[8 + j]) + al1 * __ldg(&a1r[8 + j]);
            if (j < 6) aa2 += al0 * __ldg(&a0r[16 + j]) + al1 * __ldg(&a1r[16 + j]);
        } else {
            aa0 += al0 * __ldg(&a0r[j]) + al1 * __ldg(&a1r[j]);
            if (j < 6) aa1 += al0 * __ldg(&a0r[16 + j]) + al1 * __ldg(&a1r[16 + j]);
        }
    }
    if (i < degc) {
        int p0 = e0 + i;
        int s0 = g_csrc[p0], id0 = g_ceid[p0];
        float al0 = sA[i * 8 + h];
        float4 v0 = __ldg((const float4*)&ybuf[(size_t)s0 * RS + OV + cbase + 4 * l]);
        acc.x += al0 * v0.x; acc.y += al0 * v0.y;
        acc.z += al0 * v0.z; acc.w += al0 * v0.w;
        const float* a0r = &attr[id0 * EDIM];
        if (LAYER == 1) {
            aa0 += al0 * __ldg(&a0r[j]);
            aa1 += al0 * __ldg(&a0r[8 + j]);
            if (j < 6) aa2 += al0 * __ldg(&a0r[16 + j]);
        } else {
            aa0 += al0 * __ldg(&a0r[j]);
            if (j < 6) aa1 += al0 * __ldg(&a0r[16 + j]);
        }
    }
    for (int ii = SCAP; ii < deg; ii++) {
        int p0 = e0 + ii;
        int s0 = g_csrc[p0], id0 = g_ceid[p0];
        float al0 = __expf(logit(p0) - m) * inv;
        float4 v0 = __ldg((const float4*)&ybuf[(size_t)s0 * RS + OV + cbase + 4 * l]);
        acc.x += al0 * v0.x; acc.y += al0 * v0.y;
        acc.z += al0 * v0.z; acc.w += al0 * v0.w;
        const float* a0r = &attr[id0 * EDIM];
        if (LAYER == 1) {
            aa0 += al0 * __ldg(&a0r[j]);
            aa1 += al0 * __ldg(&a0r[8 + j]);
            if (j < 6) aa2 += al0 * __ldg(&a0r[16 + j]);
        } else {
            aa0 += al0 * __ldg(&a0r[j]);
            if (j < 6) aa1 += al0 * __ldg(&a0r[16 + j]);
        }
    }

    float4 ex = make_float4(0.f, 0.f, 0.f, 0.f);
#pragma unroll
    for (int g = 0; g < 22; g++) {
        float aag;
        if (g < LPH)            aag = __shfl_sync(0xffffffffu, aa0, gb + g);
        else if (g < 2 * LPH)   aag = __shfl_sync(0xffffffffu, aa1, gb + g - LPH);
        else                    aag = __shfl_sync(0xffffffffu, aa2, gb + g - 2 * LPH);
        float4 w4 = __ldg((const float4*)&we[g * D + cbase + 4 * l]);
        ex.x += aag * w4.x; ex.y += aag * w4.y;
        ex.z += aag * w4.z; ex.w += aag * w4.w;
    }

    float4 sk = *(const float4*)&drow[OS + cbase + 4 * l];
    float4 o;
    o.x = fmaxf(sk.x + acc.x + ex.x, 0.f);
    o.y = fmaxf(sk.y + acc.y + ex.y, 0.f);
    o.z = fmaxf(sk.z + acc.z + ex.z, 0.f);
    o.w = fmaxf(sk.w + acc.w + ex.w, 0.f);

    if (LAYER == 1) {
        *(float4*)&g_x1[dst * D1 + cbase + 4 * l] = o;
    } else {
        // fused output head: sigmoid([x1 | x2] @ w_out + b)
        int c2 = cbase + 4 * l;
        float4 w4 = __ldg((const float4*)&wout[D1 + c2]);
        float part = o.x * w4.x + o.y * w4.y + o.z * w4.z + o.w * w4.w;
        // x1 contribution: 128 threads x 2 floats = 256
        int c1 = threadIdx.x * 2;
        float2 x1v = *(const float2*)&g_x1[dst * D1 + c1];
        float2 w1v = __ldg((const float2*)&wout[c1]);
        part += x1v.x * w1v.x + x1v.y * w1v.y;
#pragma unroll
        for (int of = 16; of; of >>= 1)
            part += __shfl_xor_sync(0xffffffffu, part, of);
        __shared__ float wsum[4];
        if (l == 0) wsum[w] = part;
        __syncthreads();
        if (threadIdx.x == 0) {
            float sfull = wsum[0] + wsum[1] + wsum[2] + wsum[3] + bout[0];
            out[dst] = 1.f / (1.f + expf(-sfull));
        }
    }
}

// ---------------- launch ----------------------------------------------------
extern "C" void kernel_launch(void* const* d_in, const int* in_sizes, int n_in,
                              void* d_out, int out_size) {
    const float* x  = (const float*)d_in[0];
    const int*   ei = (const int*)d_in[1];
    const float* ea = (const float*)d_in[2];
    const float* w1_q = (const float*)d_in[3];  const float* b1_q = (const float*)d_in[4];
    const float* w1_k = (const float*)d_in[5];  const float* b1_k = (const float*)d_in[6];
    const float* w1_v = (const float*)d_in[7];  const float* b1_v = (const float*)d_in[8];
    const float* w1_e = (const float*)d_in[9];
    const float* w1_s = (const float*)d_in[10]; const float* b1_s = (const float*)d_in[11];
    const float* w2_q = (const float*)d_in[12]; const float* b2_q = (const float*)d_in[13];
    const float* w2_k = (const float*)d_in[14]; const float* b2_k = (const float*)d_in[15];
    const float* w2_v = (const float*)d_in[16]; const float* b2_v = (const float*)d_in[17];
    const float* w2_e = (const float*)d_in[18];
    const float* w2_s = (const float*)d_in[19]; const float* b2_s = (const float*)d_in[20];
    const float* w_out = (const float*)d_in[21];
    const float* b_out = (const float*)d_in[22];
    float* out = (float*)d_out;

    static int smem_set = 0;
    if (!smem_set) {
        cudaFuncSetAttribute(k_gemm2_tc,
                             cudaFuncAttributeMaxDynamicSharedMemorySize, G2_SMEM);
        smem_set = 1;
    }

    k_detect<<<1, 32>>>(ei);
    k_zero_counters<<<(NN + 255) / 256, 256>>>();
    k_hist<<<(EE + 255) / 256, 256>>>(ei);
    k_scan1<<<SCB, 1024>>>();
    k_scan2<<<1, 64>>>();
    k_scan3<<<(NN + 255) / 256, 256>>>();
    k_scatter<<<(EE + 255) / 256, 256>>>(ei);

    k_wcat1<<<(FINN * W1COLS + W1COLS + 255) / 256, 256>>>(w1_q, b1_q, w1_k, b1_k,
                                                           w1_v, b1_v, w1_e, w1_s, b1_s);
    {
        dim3 g((NN + 127) / 128, (W1COLS + 127) / 128);
        k_gemm1<<<g, 256>>>(x);
    }
    k_edge<1><<<NN / 2, 128>>>(ea, w1_e, w_out, b_out, out);

    k_wcat2<<<(D1 * W2COLS + W2COLS + 255) / 256, 256>>>(w2_q, b2_q, w2_k, b2_k,
                                                         w2_v, b2_v, w2_e, w2_s, b2_s);
    {
        dim3 g((NN + 127) / 128, W2COLS / 128);
        k_gemm2_tc<<<g, 256, G2_SMEM>>>();
    }
    k_edge<2><<<NN, 128>>>(ea, w2_e, w_out, b_out, out);
}

// round 9
// speedup vs baseline: 2.3720x; 1.1437x over previous
#include <cuda_runtime.h>
#include <math.h>

#define NN   50000
#define EE   400000
#define FINN 22
#define EDIM 22
#define D1   256
#define D2   512

#define W1COLS 1200    /* q(256)|k(256)|v(256)|skip(256)|qp(176) */
#define W2COLS 2304    /* q(512)|k(512)|v(512)|skip(512)|qp(176)|pad(80) */
#define W2VALID 2224

#define SCB  49

// ---------------- scratch ----------------------------------------------------
__device__ float g_y1[NN * W1COLS];
__device__ float g_x1[NN * D1];
__device__ float g_y2[NN * W2COLS];
__device__ int   g_deg[NN];
__device__ int   g_cur[NN];
__device__ int   g_off[NN + 1];
__device__ int   g_csrc[EE];
__device__ int   g_ceid[EE];
__device__ float g_wcat1[FINN * W1COLS];
__device__ float g_bcat1[W1COLS];
__device__ float g_wcat2[D1 * W2COLS];
__device__ float g_bcat2[W2COLS];
__device__ int   g_is64;
__device__ int   g_bsum[SCB];
__device__ int   g_bbase[SCB];

// ---------------- edge_index dtype detection --------------------------------
__global__ void k_detect(const int* __restrict__ ei) {
    int l = threadIdx.x;
    int nz = 0;
    for (int i = l; i < 1024; i += 32) nz |= (ei[2 * i + 1] != 0);
    unsigned m = __ballot_sync(0xffffffffu, nz);
    if (l == 0) g_is64 = (m == 0);
}
__device__ __forceinline__ int ld_src(const int* __restrict__ ei, int e) {
    return g_is64 ? ei[2 * e] : ei[e];
}
__device__ __forceinline__ int ld_dst(const int* __restrict__ ei, int e) {
    return g_is64 ? ei[2 * (EE + e)] : ei[EE + e];
}

// ---------------- CSR build ----------------
__global__ void k_zero_counters() {
    int i = blockIdx.x * blockDim.x + threadIdx.x;
    if (i < NN) { g_deg[i] = 0; g_cur[i] = 0; }
}
__global__ void k_hist(const int* __restrict__ ei) {
    int e = blockIdx.x * blockDim.x + threadIdx.x;
    if (e < EE) atomicAdd(&g_deg[ld_dst(ei, e)], 1);
}
__global__ void k_scan1() {
    __shared__ int sm[1024];
    int b = blockIdx.x;
    int i = b * 1024 + threadIdx.x;
    int v = (i < NN) ? g_deg[i] : 0;
    sm[threadIdx.x] = v;
    __syncthreads();
    for (int off = 1; off < 1024; off <<= 1) {
        int t = 0;
        if (threadIdx.x >= off) t = sm[threadIdx.x - off];
        __syncthreads();
        if (threadIdx.x >= off) sm[threadIdx.x] += t;
        __syncthreads();
    }
    if (i < NN) g_off[i + 1] = sm[threadIdx.x];
    if (threadIdx.x == 1023) g_bsum[b] = sm[1023];
}
__global__ void k_scan2() {
    if (threadIdx.x == 0) {
        int run = 0;
        for (int b = 0; b < SCB; b++) { g_bbase[b] = run; run += g_bsum[b]; }
        g_off[0] = 0;
    }
}
__global__ void k_scan3() {
    int i = blockIdx.x * blockDim.x + threadIdx.x;
    if (i < NN) g_off[i + 1] += g_bbase[i >> 10];
}
__global__ void k_scatter(const int* __restrict__ ei) {
    int e = blockIdx.x * blockDim.x + threadIdx.x;
    if (e < EE) {
        int src = ld_src(ei, e);
        int dst = ld_dst(ei, e);
        int pos = g_off[dst] + atomicAdd(&g_cur[dst], 1);
        g_csrc[pos] = src;
        g_ceid[pos] = e;
    }
}

// ---------------- weight concat builders -------------------------------------
__global__ void k_wcat1(const float* __restrict__ wq, const float* __restrict__ bq,
                        const float* __restrict__ wk, const float* __restrict__ bk,
                        const float* __restrict__ wv, const float* __restrict__ bv,
                        const float* __restrict__ we,
                        const float* __restrict__ ws, const float* __restrict__ bs) {
    int idx = blockIdx.x * blockDim.x + threadIdx.x;
    int wn = FINN * W1COLS;
    if (idx < wn) {
        int f = idx / W1COLS, c = idx % W1COLS;
        float val;
        if (c < 256)       val = wq[f * 256 + c];
        else if (c < 512)  val = wk[f * 256 + (c - 256)];
        else if (c < 768)  val = wv[f * 256 + (c - 512)];
        else if (c < 1024) val = ws[f * 256 + (c - 768)];
        else {
            int t = c - 1024, h = t / 22, g = t % 22;
            float s = 0.f;
            for (int cc = 0; cc < 32; cc++)
                s += wq[f * 256 + h * 32 + cc] * we[g * 256 + h * 32 + cc];
            val = s;
        }
        g_wcat1[f * W1COLS + c] = val;
    } else if (idx < wn + W1COLS) {
        int c = idx - wn;
        float val;
        if (c < 256)       val = bq[c];
        else if (c < 512)  val = bk[c - 256];
        else if (c < 768)  val = bv[c - 512];
        else if (c < 1024) val = bs[c - 768];
        else {
            int t = c - 1024, h = t / 22, g = t % 22;
            float s = 0.f;
            for (int cc = 0; cc < 32; cc++)
                s += bq[h * 32 + cc] * we[g * 256 + h * 32 + cc];
            val = s;
        }
        g_bcat1[c] = val;
    }
}

__global__ void k_wcat2(const float* __restrict__ wq, const float* __restrict__ bq,
                        const float* __restrict__ wk, const float* __restrict__ bk,
                        const float* __restrict__ wv, const float* __restrict__ bv,
                        const float* __restrict__ we,
                        const float* __restrict__ ws, const float* __restrict__ bs) {
    int idx = blockIdx.x * blockDim.x + threadIdx.x;
    int wn = D1 * W2COLS;
    if (idx < wn) {
        int f = idx / W2COLS, c = idx % W2COLS;
        float val = 0.f;
        if (c < 512)        val = wq[f * 512 + c];
        else if (c < 1024)  val = wk[f * 512 + (c - 512)];
        else if (c < 1536)  val = wv[f * 512 + (c - 1024)];
        else if (c < 2048)  val = ws[f * 512 + (c - 1536)];
        else if (c < W2VALID) {
            int t = c - 2048, h = t / 22, g = t % 22;
            float s = 0.f;
            for (int cc = 0; cc < 64; cc++)
                s += wq[f * 512 + h * 64 + cc] * we[g * 512 + h * 64 + cc];
            val = s;
        }
        g_wcat2[f * W2COLS + c] = val;
    } else if (idx < wn + W2COLS) {
        int c = idx - wn;
        float val = 0.f;
        if (c < 512)        val = bq[c];
        else if (c < 1024)  val = bk[c - 512];
        else if (c < 1536)  val = bv[c - 1024];
        else if (c < 2048)  val = bs[c - 1536];
        else if (c < W2VALID) {
            int t = c - 2048, h = t / 22, g = t % 22;
            float s = 0.f;
            for (int cc = 0; cc < 64; cc++)
                s += bq[h * 64 + cc] * we[g * 512 + h * 64 + cc];
            val = s;
        }
        g_bcat2[c] = val;
    }
}

// ---------------- layer1 node GEMM -> g_y1 -----------------------------------
__global__ void __launch_bounds__(256) k_gemm1(const float* __restrict__ x) {
    __shared__ float xs[FINN][128];
    __shared__ float ws[FINN][128];
    int m0 = blockIdx.x * 128;
    int c0 = blockIdx.y * 128;
    int t = threadIdx.x;
    for (int i = t; i < 128 * FINN; i += 256) {
        int n = i / FINN, f = i % FINN;
        xs[f][n] = (m0 + n < NN) ? x[(m0 + n) * FINN + f] : 0.f;
    }
    for (int i = t; i < FINN * 128; i += 256) {
        int f = i / 128, cc = i % 128;
        ws[f][cc] = (c0 + cc < W1COLS) ? g_wcat1[f * W1COLS + c0 + cc] : 0.f;
    }
    __syncthreads();
    int tr = t >> 4, tc = t & 15;
    float acc[8][8];
#pragma unroll
    for (int i = 0; i < 8; i++)
#pragma unroll
        for (int j = 0; j < 8; j++) acc[i][j] = 0.f;
#pragma unroll
    for (int f = 0; f < FINN; f++) {
        float a[8], b[8];
        *(float4*)(a)     = *(const float4*)&xs[f][tr * 8];
        *(float4*)(a + 4) = *(const float4*)&xs[f][tr * 8 + 4];
        *(float4*)(b)     = *(const float4*)&ws[f][tc * 8];
        *(float4*)(b + 4) = *(const float4*)&ws[f][tc * 8 + 4];
#pragma unroll
        for (int i = 0; i < 8; i++)
#pragma unroll
            for (int j = 0; j < 8; j++) acc[i][j] += a[i] * b[j];
    }
    int cb = c0 + tc * 8;
    float bb[8];
    if (cb + 7 < W1COLS) {
        *(float4*)(bb)     = *(const float4*)&g_bcat1[cb];
        *(float4*)(bb + 4) = *(const float4*)&g_bcat1[cb + 4];
#pragma unroll
        for (int i = 0; i < 8; i++) {
            int row = m0 + tr * 8 + i;
            if (row >= NN) continue;
            float4 o0 = make_float4(acc[i][0] + bb[0], acc[i][1] + bb[1],
                                    acc[i][2] + bb[2], acc[i][3] + bb[3]);
            float4 o1 = make_float4(acc[i][4] + bb[4], acc[i][5] + bb[5],
                                    acc[i][6] + bb[6], acc[i][7] + bb[7]);
            *(float4*)&g_y1[row * W1COLS + cb]     = o0;
            *(float4*)&g_y1[row * W1COLS + cb + 4] = o1;
        }
    }
}

// ---------------- layer2 GEMM: tf32 mma + cp.async -> g_y2 -------------------
__device__ __forceinline__ void mma_tf32(float* c, unsigned a0, unsigned a1,
                                         unsigned a2, unsigned a3,
                                         unsigned b0, unsigned b1) {
    asm volatile("mma.sync.aligned.m16n8k8.row.col.f32.tf32.tf32.f32 "
                 "{%0,%1,%2,%3}, {%4,%5,%6,%7}, {%8,%9}, {%0,%1,%2,%3};"
                 : "+f"(c[0]), "+f"(c[1]), "+f"(c[2]), "+f"(c[3])
                 : "r"(a0), "r"(a1), "r"(a2), "r"(a3), "r"(b0), "r"(b1));
}
__device__ __forceinline__ void cp16(void* sptr, const void* gptr) {
    unsigned sa = (unsigned)__cvta_generic_to_shared(sptr);
    asm volatile("cp.async.cg.shared.global [%0], [%1], 16;" :: "r"(sa), "l"(gptr));
}

#define ASTRIDE 36
#define BSTRIDE 136
#define ASZ (128 * ASTRIDE)
#define BSZ (32 * BSTRIDE)
#define G2_SMEM ((2 * ASZ + 2 * BSZ) * 4)

__global__ void __launch_bounds__(256) k_gemm2_tc() {
    extern __shared__ float sm[];
    float* As[2] = { sm, sm + ASZ };
    float* Bs[2] = { sm + 2 * ASZ, sm + 2 * ASZ + BSZ };

    int m0 = blockIdx.x * 128;
    int c0 = blockIdx.y * 128;
    int t = threadIdx.x;
    int w = t >> 5, l = t & 31;
    int wm = (w >> 2) * 64;
    int wn = (w & 3) * 32;
    int gp = l >> 2, tq = l & 3;

    float acc[4][4][4];
#pragma unroll
    for (int a = 0; a < 4; a++)
#pragma unroll
        for (int b = 0; b < 4; b++)
#pragma unroll
            for (int cc = 0; cc < 4; cc++) acc[a][b][cc] = 0.f;

    auto load_stage = [&](int kc, int s) {
#pragma unroll
        for (int li = 0; li < 4; li++) {
            int idx = t + li * 256;
            int m = idx >> 3, kq = (idx & 7) * 4;
            float* sp = &As[s][m * ASTRIDE + kq];
            if (m0 + m < NN)
                cp16(sp, &g_x1[(m0 + m) * D1 + kc * 32 + kq]);
            else
                *(float4*)sp = make_float4(0.f, 0.f, 0.f, 0.f);
        }
#pragma unroll
        for (int li = 0; li < 4; li++) {
            int idx = t + li * 256;
            int r = idx >> 5, c4 = (idx & 31) * 4;
            cp16(&Bs[s][r * BSTRIDE + c4],
                 &g_wcat2[(kc * 32 + r) * W2COLS + c0 + c4]);
        }
    };

    load_stage(0, 0);
    asm volatile("cp.async.commit_group;");

    for (int kc = 0; kc < 8; kc++) {
        int cur = kc & 1;
        if (kc < 7) {
            load_stage(kc + 1, cur ^ 1);
            asm volatile("cp.async.commit_group;");
            asm volatile("cp.async.wait_group 1;");
        } else {
            asm volatile("cp.async.wait_group 0;");
        }
        __syncthreads();
        const float* A = As[cur];
        const float* B = Bs[cur];
#pragma unroll
        for (int kb = 0; kb < 4; kb++) {
            int k0 = kb * 8;
            unsigned af[4][4], bf[4][2];
#pragma unroll
            for (int mt = 0; mt < 4; mt++) {
                int row = wm + mt * 16 + gp;
                af[mt][0] = __float_as_uint(A[row * ASTRIDE + k0 + tq]);
                af[mt][1] = __float_as_uint(A[(row + 8) * ASTRIDE + k0 + tq]);
                af[mt][2] = __float_as_uint(A[row * ASTRIDE + k0 + tq + 4]);
                af[mt][3] = __float_as_uint(A[(row + 8) * ASTRIDE + k0 + tq + 4]);
            }
#pragma unroll
            for (int nt = 0; nt < 4; nt++) {
                int col = wn + nt * 8 + gp;
                bf[nt][0] = __float_as_uint(B[(k0 + tq) * BSTRIDE + col]);
                bf[nt][1] = __float_as_uint(B[(k0 + tq + 4) * BSTRIDE + col]);
            }
#pragma unroll
            for (int mt = 0; mt < 4; mt++)
#pragma unroll
                for (int nt = 0; nt < 4; nt++)
                    mma_tf32(acc[mt][nt], af[mt][0], af[mt][1], af[mt][2],
                             af[mt][3], bf[nt][0], bf[nt][1]);
        }
        __syncthreads();
    }
#pragma unroll
    for (int mt = 0; mt < 4; mt++) {
        int r0 = m0 + wm + mt * 16 + gp;
#pragma unroll
        for (int nt = 0; nt < 4; nt++) {
            int cb = c0 + wn + nt * 8 + tq * 2;
            float b0 = g_bcat2[cb], b1 = g_bcat2[cb + 1];
            if (r0 < NN)
                *(float2*)&g_y2[r0 * W2COLS + cb] =
                    make_float2(acc[mt][nt][0] + b0, acc[mt][nt][1] + b1);
            if (r0 + 8 < NN)
                *(float2*)&g_y2[(r0 + 8) * W2COLS + cb] =
                    make_float2(acc[mt][nt][2] + b0, acc[mt][nt][3] + b1);
        }
    }
}

// ---------------- fused attention: single-pass flash-style softmax -----------
// LAYER==2 also fuses the output head.
template <int LAYER>
__global__ void __launch_bounds__(128) k_edge(const float* __restrict__ attr,
                                              const float* __restrict__ we,
                                              const float* __restrict__ wout,
                                              const float* __restrict__ bout,
                                              float* __restrict__ out) {
    constexpr int C   = (LAYER == 1) ? 32 : 64;
    constexpr int D   = 8 * C;
    constexpr int RS  = (LAYER == 1) ? W1COLS : W2COLS;
    constexpr int OK  = D;
    constexpr int OV  = 2 * D;
    constexpr int OS  = 3 * D;
    constexpr int OQP = 4 * D;
    constexpr int LPH = (LAYER == 1) ? 8 : 16;
    constexpr int NPB = (LAYER == 1) ? 2 : 1;
    constexpr int WPN = 4 / NPB;
    const float* ybuf = (LAYER == 1) ? g_y1 : g_y2;
    const float scale = (LAYER == 1) ? 0.17677669529663687f : 0.125f;

    int w = threadIdx.x >> 5, l = threadIdx.x & 31;
    int node = w / WPN;
    int wl = w % WPN;
    int dst = blockIdx.x * NPB + node;
    int cbase = wl * 128;
    int h = (LAYER == 1) ? (wl * 4 + (l >> 3)) : (wl * 2 + (l >> 4));
    int j = l & (LPH - 1);
    int gb = l & ~(LPH - 1);

    int e0 = g_off[dst], deg = g_off[dst + 1] - e0;
    const float* drow = &ybuf[(size_t)dst * RS];

    float4 q4 = *(const float4*)&drow[cbase + 4 * l];
    const float* qp = &drow[OQP + h * 22];
    float qp0, qp1, qp2 = 0.f;
    if (LAYER == 1) {
        qp0 = qp[j]; qp1 = qp[8 + j]; qp2 = (j < 6) ? qp[16 + j] : 0.f;
    } else {
        qp0 = qp[j]; qp1 = (j < 6) ? qp[16 + j] : 0.f;
    }

    float m = -1e30f, s = 0.f;
    float4 acc = make_float4(0.f, 0.f, 0.f, 0.f);
    float aa0 = 0.f, aa1 = 0.f, aa2 = 0.f;

    // logits + value fetch in one shot; a0/a1/a2 are this lane's attr entries
    auto body = [&](int pos, float& t, float4& v4, float& a0, float& a1, float& a2) {
        int srcn = g_csrc[pos];
        int eid = g_ceid[pos];
        const float* srow = &ybuf[(size_t)srcn * RS];
        float4 k4 = __ldg((const float4*)&srow[OK + cbase + 4 * l]);
        v4 = __ldg((const float4*)&srow[OV + cbase + 4 * l]);
        const float* ar = &attr[eid * EDIM];
        if (LAYER == 1) {
            a0 = __ldg(&ar[j]); a1 = __ldg(&ar[8 + j]);
            a2 = (j < 6) ? __ldg(&ar[16 + j]) : 0.f;
            t = q4.x * k4.x + q4.y * k4.y + q4.z * k4.z + q4.w * k4.w
              + a0 * qp0 + a1 * qp1 + a2 * qp2;
        } else {
            a0 = __ldg(&ar[j]);
            a1 = (j < 6) ? __ldg(&ar[16 + j]) : 0.f;
            a2 = 0.f;
            t = q4.x * k4.x + q4.y * k4.y + q4.z * k4.z + q4.w * k4.w
              + a0 * qp0 + a1 * qp1;
        }
#pragma unroll
        for (int o = LPH / 2; o; o >>= 1)
            t += __shfl_xor_sync(0xffffffffu, t, o);
        t *= scale;
    };

    int i = 0;
    for (; i + 2 <= deg; i += 2) {
        float t0, t1;
        float4 v0, v1;
        float a00, a01, a02, a10, a11, a12;
        body(e0 + i,     t0, v0, a00, a01, a02);
        body(e0 + i + 1, t1, v1, a10, a11, a12);
        float nm = fmaxf(m, fmaxf(t0, t1));
        float c  = __expf(m - nm);
        float p0 = __expf(t0 - nm);
        float p1 = __expf(t1 - nm);
        s = s * c + p0 + p1;
        acc.x = acc.x * c + p0 * v0.x + p1 * v1.x;
        acc.y = acc.y * c + p0 * v0.y + p1 * v1.y;
        acc.z = acc.z * c + p0 * v0.z + p1 * v1.z;
        acc.w = acc.w * c + p0 * v0.w + p1 * v1.w;
        aa0 = aa0 * c + p0 * a00 + p1 * a10;
        aa1 = aa1 * c + p0 * a01 + p1 * a11;
        if (LAYER == 1) aa2 = aa2 * c + p0 * a02 + p1 * a12;
        m = nm;
    }
    if (i < deg) {
        float t0;
        float4 v0;
        float a00, a01, a02;
        body(e0 + i, t0, v0, a00, a01, a02);
        float nm = fmaxf(m, t0);
        float c  = __expf(m - nm);
        float p0 = __expf(t0 - nm);
        s = s * c + p0;
        acc.x = acc.x * c + p0 * v0.x;
        acc.y = acc.y * c + p0 * v0.y;
        acc.z = acc.z * c + p0 * v0.z;
        acc.w = acc.w * c + p0 * v0.w;
        aa0 = aa0 * c + p0 * a00;
        aa1 = aa1 * c + p0 * a01;
        if (LAYER == 1) aa2 = aa2 * c + p0 * a02;
        m = nm;
    }

    float inv = 1.f / (s + 1e-16f);
    acc.x *= inv; acc.y *= inv; acc.z *= inv; acc.w *= inv;
    aa0 *= inv; aa1 *= inv; aa2 *= inv;

    // attr-message: out_h += (sum_e alpha_eh * attr_e) @ We_h
    float4 ex = make_float4(0.f, 0.f, 0.f, 0.f);
#pragma unroll
    for (int g = 0; g < 22; g++) {
        float aag;
        if (g < LPH)            aag = __shfl_sync(0xffffffffu, aa0, gb + g);
        else if (g < 2 * LPH)   aag = __shfl_sync(0xffffffffu, aa1, gb + g - LPH);
        else                    aag = __shfl_sync(0xffffffffu, aa2, gb + g - 2 * LPH);
        float4 w4 = __ldg((const float4*)&we[g * D + cbase + 4 * l]);
        ex.x += aag * w4.x; ex.y += aag * w4.y;
        ex.z += aag * w4.z; ex.w += aag * w4.w;
    }

    float4 sk = *(const float4*)&drow[OS + cbase + 4 * l];
    float4 o;
    o.x = fmaxf(sk.x + acc.x + ex.x, 0.f);
    o.y = fmaxf(sk.y + acc.y + ex.y, 0.f);
    o.z = fmaxf(sk.z + acc.z + ex.z, 0.f);
    o.w = fmaxf(sk.w + acc.w + ex.w, 0.f);

    if (LAYER == 1) {
        *(float4*)&g_x1[dst * D1 + cbase + 4 * l] = o;
    } else {
        // fused output head: sigmoid([x1 | x2] @ w_out + b)
        int c2 = cbase + 4 * l;
        float4 w4 = __ldg((const float4*)&wout[D1 + c2]);
        float part = o.x * w4.x + o.y * w4.y + o.z * w4.z + o.w * w4.w;
        int c1 = threadIdx.x * 2;
        float2 x1v = *(const float2*)&g_x1[dst * D1 + c1];
        float2 w1v = __ldg((const float2*)&wout[c1]);
        part += x1v.x * w1v.x + x1v.y * w1v.y;
#pragma unroll
        for (int of = 16; of; of >>= 1)
            part += __shfl_xor_sync(0xffffffffu, part, of);
        __shared__ float wsum[4];
        if (l == 0) wsum[w] = part;
        __syncthreads();
        if (threadIdx.x == 0) {
            float sfull = wsum[0] + wsum[1] + wsum[2] + wsum[3] + bout[0];
            out[dst] = 1.f / (1.f + expf(-sfull));
        }
    }
}

// ---------------- launch ----------------------------------------------------
extern "C" void kernel_launch(void* const* d_in, const int* in_sizes, int n_in,
                              void* d_out, int out_size) {
    const float* x  = (const float*)d_in[0];
    const int*   ei = (const int*)d_in[1];
    const float* ea = (const float*)d_in[2];
    const float* w1_q = (const float*)d_in[3];  const float* b1_q = (const float*)d_in[4];
    const float* w1_k = (const float*)d_in[5];  const float* b1_k = (const float*)d_in[6];
    const float* w1_v = (const float*)d_in[7];  const float* b1_v = (const float*)d_in[8];
    const float* w1_e = (const float*)d_in[9];
    const float* w1_s = (const float*)d_in[10]; const float* b1_s = (const float*)d_in[11];
    const float* w2_q = (const float*)d_in[12]; const float* b2_q = (const float*)d_in[13];
    const float* w2_k = (const float*)d_in[14]; const float* b2_k = (const float*)d_in[15];
    const float* w2_v = (const float*)d_in[16]; const float* b2_v = (const float*)d_in[17];
    const float* w2_e = (const float*)d_in[18];
    const float* w2_s = (const float*)d_in[19]; const float* b2_s = (const float*)d_in[20];
    const float* w_out = (const float*)d_in[21];
    const float* b_out = (const float*)d_in[22];
    float* out = (float*)d_out;

    static int smem_set = 0;
    if (!smem_set) {
        cudaFuncSetAttribute(k_gemm2_tc,
                             cudaFuncAttributeMaxDynamicSharedMemorySize, G2_SMEM);
        smem_set = 1;
    }

    k_detect<<<1, 32>>>(ei);
    k_zero_counters<<<(NN + 255) / 256, 256>>>();
    k_hist<<<(EE + 255) / 256, 256>>>(ei);
    k_scan1<<<SCB, 1024>>>();
    k_scan2<<<1, 64>>>();
    k_scan3<<<(NN + 255) / 256, 256>>>();
    k_scatter<<<(EE + 255) / 256, 256>>>(ei);

    k_wcat1<<<(FINN * W1COLS + W1COLS + 255) / 256, 256>>>(w1_q, b1_q, w1_k, b1_k,
                                                           w1_v, b1_v, w1_e, w1_s, b1_s);
    {
        dim3 g((NN + 127) / 128, (W1COLS + 127) / 128);
        k_gemm1<<<g, 256>>>(x);
    }
    k_edge<1><<<NN / 2, 128>>>(ea, w1_e, w_out, b_out, out);

    k_wcat2<<<(D1 * W2COLS + W2COLS + 255) / 256, 256>>>(w2_q, b2_q, w2_k, b2_k,
                                                         w2_v, b2_v, w2_e, w2_s, b2_s);
    {
        dim3 g((NN + 127) / 128, W2COLS / 128);
        k_gemm2_tc<<<g, 256, G2_SMEM>>>();
    }
    k_edge<2><<<NN, 128>>>(ea, w2_e, w_out, b_out, out);
}